// round 4
// baseline (speedup 1.0000x reference)
#include <cuda_runtime.h>
#include <math.h>
#include <stdint.h>

typedef unsigned long long u64;

// ---- packed f32x2 FMA helpers (Blackwell) ----
__device__ __forceinline__ u64 dup2(float x) {
    u64 r; asm("mov.b64 %0, {%1,%2};" : "=l"(r) : "f"(x), "f"(x)); return r;
}
__device__ __forceinline__ u64 ffma2(u64 a, u64 b, u64 c) {
    u64 d; asm("fma.rn.f32x2 %0, %1, %2, %3;" : "=l"(d) : "l"(a), "l"(b), "l"(c)); return d;
}
__device__ __forceinline__ float2 unpack2(u64 v) {
    float2 f; asm("mov.b64 {%0,%1}, %2;" : "=f"(f.x), "=f"(f.y) : "l"(v)); return f;
}

#define T_SEQ 200
#define BATCH 128
#define MROWS (T_SEQ * BATCH)   // 25600

// ---- device-global scratch ----
__device__ float g_x0[MROWS * 400];
__device__ float g_xg[(size_t)MROWS * 4600];
__device__ float g_c[BATCH * 1150];
__device__ float g_h0[BATCH * 1150];

// ---------------------------------------------------------------------------
__global__ void zero_kernel(float* __restrict__ p, int n) {
    int i = blockIdx.x * blockDim.x + threadIdx.x;
    if (i < n) p[i] = 0.0f;
}

__global__ void embed_kernel(const int* __restrict__ tokens,
                             const float* __restrict__ emb,
                             float* __restrict__ x) {
    int row = blockIdx.x;
    int tok = tokens[row];
    const float4* s = (const float4*)(emb + (size_t)tok * 400);
    float4* d = (float4*)(x + (size_t)row * 400);
    for (int i = threadIdx.x; i < 100; i += blockDim.x) d[i] = s[i];
}

// ===========================================================================
// mma.sync tf32 helpers (plain sm_103-compatible)
// ===========================================================================
__device__ __forceinline__ uint32_t cvt_tf32(float x) {
    uint32_t u; asm("cvt.rna.tf32.f32 %0, %1;" : "=r"(u) : "f"(x)); return u;
}
__device__ __forceinline__ void mma_tf32(float* d, const uint32_t* a,
                                         uint32_t b0, uint32_t b1) {
    asm volatile(
        "mma.sync.aligned.m16n8k8.row.col.f32.tf32.tf32.f32 "
        "{%0,%1,%2,%3}, {%4,%5,%6,%7}, {%8,%9}, {%0,%1,%2,%3};"
        : "+f"(d[0]), "+f"(d[1]), "+f"(d[2]), "+f"(d[3])
        : "r"(a[0]), "r"(a[1]), "r"(a[2]), "r"(a[3]), "r"(b0), "r"(b1));
}

// ===========================================================================
// 3xTF32 mma.sync GEMM:  C[M,Ntot] = A[M,K] @ W[Ntot,K]^T + bias
// 128x128 CTA tile, BK=32, 8 warps (warp tile 32x64), double-buffered.
// smem layout per stage (u32): Ahi | Alo | Bhi | Blo, each [32][136] k-major.
// ===========================================================================
#define BM 128
#define BN 128
#define BKC 32
#define ASP 136
#define A_HI 0
#define A_LO 4352
#define B_HI 8704
#define B_LO 13056
#define ST_U32 17408
#define DYN_SMEM ((2 * ST_U32 + 128) * 4)   // 139776 B

__device__ __forceinline__ void ldg_chunk(
    const float* __restrict__ A, const float* __restrict__ W,
    int Ntot, int K, int m0, int n0, int k0,
    float2* ra, float2* rb, int tid)
{
#pragma unroll
    for (int it = 0; it < 8; ++it) {
        int g = tid + it * 256;
        int r = g >> 4, c2 = g & 15;
        int k = k0 + c2 * 2;
        float2 v = make_float2(0.0f, 0.0f);
        if (k + 1 < K)      v = *(const float2*)(A + (size_t)(m0 + r) * K + k);
        else if (k < K)     v.x = A[(size_t)(m0 + r) * K + k];
        ra[it] = v;
        int n = n0 + r;
        float2 w = make_float2(0.0f, 0.0f);
        if (n < Ntot) {
            if (k + 1 < K)  w = *(const float2*)(W + (size_t)n * K + k);
            else if (k < K) w.x = W[(size_t)n * K + k];
        }
        rb[it] = w;
    }
}

__device__ __forceinline__ void sts_chunk(uint32_t* st, const float2* ra,
                                          const float2* rb, int tid)
{
#pragma unroll
    for (int it = 0; it < 8; ++it) {
        int g = tid + it * 256;
        int r = g >> 4, c2 = g & 15;
        float2 v = ra[it];
        uint32_t hx = cvt_tf32(v.x), hy = cvt_tf32(v.y);
        st[A_HI + (c2 * 2) * ASP + r]     = hx;
        st[A_HI + (c2 * 2 + 1) * ASP + r] = hy;
        st[A_LO + (c2 * 2) * ASP + r]     = cvt_tf32(v.x - __uint_as_float(hx));
        st[A_LO + (c2 * 2 + 1) * ASP + r] = cvt_tf32(v.y - __uint_as_float(hy));
        float2 w = rb[it];
        hx = cvt_tf32(w.x); hy = cvt_tf32(w.y);
        st[B_HI + (c2 * 2) * ASP + r]     = hx;
        st[B_HI + (c2 * 2 + 1) * ASP + r] = hy;
        st[B_LO + (c2 * 2) * ASP + r]     = cvt_tf32(w.x - __uint_as_float(hx));
        st[B_LO + (c2 * 2 + 1) * ASP + r] = cvt_tf32(w.y - __uint_as_float(hy));
    }
}

extern __shared__ uint32_t us[];

__global__ __launch_bounds__(256) void gemm_mma(
    const float* __restrict__ A, const float* __restrict__ W,
    const float* __restrict__ bias, float* __restrict__ C,
    int M, int Ntot, int K)
{
    const int tid = threadIdx.x;
    const int lane = tid & 31;
    const int wid = tid >> 5;
    const int qt = lane & 3;       // thread-in-group
    const int qd = lane >> 2;      // group id
    const int n0 = blockIdx.x * BN;
    const int m0 = blockIdx.y * BM;
    const int wm = (wid >> 1) * 32;
    const int wn = (wid & 1) * 64;

    float* bs = (float*)(us + 2 * ST_U32);
    if (tid < BN) { int n = n0 + tid; bs[tid] = (n < Ntot) ? bias[n] : 0.0f; }

    float acc[2][8][4];
#pragma unroll
    for (int mt = 0; mt < 2; ++mt)
#pragma unroll
        for (int ntl = 0; ntl < 8; ++ntl)
#pragma unroll
            for (int e = 0; e < 4; ++e) acc[mt][ntl][e] = 0.0f;

    const int nt = (K + BKC - 1) / BKC;
    float2 ra[8], rb[8];

    // prologue: chunk 0 -> stage 0
    ldg_chunk(A, W, Ntot, K, m0, n0, 0, ra, rb, tid);
    sts_chunk(us, ra, rb, tid);
    __syncthreads();

    for (int i = 0; i < nt; ++i) {
        uint32_t* st = us + (i & 1) * ST_U32;
        const bool more = (i + 1 < nt);
        if (more) ldg_chunk(A, W, Ntot, K, m0, n0, (i + 1) * BKC, ra, rb, tid);

#pragma unroll
        for (int kk = 0; kk < BKC; kk += 8) {
            const int kr = kk + qt;
            uint32_t ah[2][4], al[2][4];
#pragma unroll
            for (int mt = 0; mt < 2; ++mt) {
                int mb = wm + mt * 16 + qd;
                ah[mt][0] = st[A_HI + kr * ASP + mb];
                ah[mt][1] = st[A_HI + kr * ASP + mb + 8];
                ah[mt][2] = st[A_HI + (kr + 4) * ASP + mb];
                ah[mt][3] = st[A_HI + (kr + 4) * ASP + mb + 8];
                al[mt][0] = st[A_LO + kr * ASP + mb];
                al[mt][1] = st[A_LO + kr * ASP + mb + 8];
                al[mt][2] = st[A_LO + (kr + 4) * ASP + mb];
                al[mt][3] = st[A_LO + (kr + 4) * ASP + mb + 8];
            }
#pragma unroll
            for (int ntl = 0; ntl < 8; ++ntl) {
                int nb = wn + ntl * 8 + qd;
                uint32_t bh0 = st[B_HI + kr * ASP + nb];
                uint32_t bh1 = st[B_HI + (kr + 4) * ASP + nb];
                uint32_t bl0 = st[B_LO + kr * ASP + nb];
                uint32_t bl1 = st[B_LO + (kr + 4) * ASP + nb];
#pragma unroll
                for (int mt = 0; mt < 2; ++mt) {
                    mma_tf32(acc[mt][ntl], ah[mt], bh0, bh1);
                    mma_tf32(acc[mt][ntl], ah[mt], bl0, bl1);
                    mma_tf32(acc[mt][ntl], al[mt], bh0, bh1);
                }
            }
        }

        if (more) sts_chunk(us + ((i + 1) & 1) * ST_U32, ra, rb, tid);
        __syncthreads();
    }

    // epilogue: direct float2 stores + bias
#pragma unroll
    for (int mt = 0; mt < 2; ++mt) {
        int row = m0 + wm + mt * 16 + qd;
#pragma unroll
        for (int ntl = 0; ntl < 8; ++ntl) {
            int nc = wn + ntl * 8 + qt * 2;
            int col = n0 + nc;
            if (col < Ntot) {
                float b0 = bs[nc], b1 = bs[nc + 1];
                float2 v0 = make_float2(acc[mt][ntl][0] + b0, acc[mt][ntl][1] + b1);
                float2 v1 = make_float2(acc[mt][ntl][2] + b0, acc[mt][ntl][3] + b1);
                *(float2*)(C + (size_t)row * Ntot + col) = v0;
                *(float2*)(C + (size_t)(row + 8) * Ntot + col) = v1;
            }
        }
    }
}

// ---------------------------------------------------------------------------
// One LSTM timestep, fused GEMM + gates (SIMT f32x2, double-buffered).
#define LAST 66
#define LBST 33
__global__ __launch_bounds__(128) void lstm_step(
    const float* __restrict__ xg_t, const float* __restrict__ h_prev,
    const float* __restrict__ W_hh, float* __restrict__ h_out,
    float* __restrict__ c_state, int H)
{
    __shared__ float As[2 * 16 * LAST];
    __shared__ float Bs[2 * 16 * LBST];

    const int tid = threadIdx.x;
    const int hh0 = blockIdx.x * 8;
    const int rowoff = blockIdx.y * 64;
    const int j  = tid & 7;
    const int rg = tid >> 3;
    const int lk = tid & 15;
    const int lr = tid >> 4;

    u64 acc[2][4];
#pragma unroll
    for (int p = 0; p < 2; ++p)
#pragma unroll
        for (int g = 0; g < 4; ++g) acc[p][g] = 0ull;

    const int nt = (H + 15) >> 4;
    float ra[8], rbw[4];

    {
        const int k = lk;
#pragma unroll
        for (int p = 0; p < 8; ++p)
            ra[p] = h_prev[(size_t)(rowoff + lr + p * 8) * H + k];
#pragma unroll
        for (int p = 0; p < 4; ++p) {
            int col = lr + p * 8;
            int g = col >> 3, jj = col & 7;
            rbw[p] = (hh0 + jj < H) ? W_hh[(size_t)(g * H + hh0 + jj) * H + k] : 0.0f;
        }
#pragma unroll
        for (int p = 0; p < 8; ++p) As[lk * LAST + lr + p * 8] = ra[p];
#pragma unroll
        for (int p = 0; p < 4; ++p) Bs[lk * LBST + lr + p * 8] = rbw[p];
    }
    __syncthreads();

    for (int i = 0; i < nt; ++i) {
        const int cur = i & 1;
        const bool more = (i + 1 < nt);
        if (more) {
            const int k = (i + 1) * 16 + lk;
            const bool kin = (k < H);
#pragma unroll
            for (int p = 0; p < 8; ++p)
                ra[p] = kin ? h_prev[(size_t)(rowoff + lr + p * 8) * H + k] : 0.0f;
#pragma unroll
            for (int p = 0; p < 4; ++p) {
                int col = lr + p * 8;
                int g = col >> 3, jj = col & 7;
                rbw[p] = (kin && hh0 + jj < H)
                       ? W_hh[(size_t)(g * H + hh0 + jj) * H + k] : 0.0f;
            }
        }

        const float* Ac = As + cur * 16 * LAST;
        const float* Bc = Bs + cur * 16 * LBST;
#pragma unroll
        for (int kk = 0; kk < 16; ++kk) {
            u64 a0 = *(const u64*)&Ac[kk * LAST + rg * 4];
            u64 a1 = *(const u64*)&Ac[kk * LAST + rg * 4 + 2];
#pragma unroll
            for (int g = 0; g < 4; ++g) {
                u64 bb = dup2(Bc[kk * LBST + g * 8 + j]);
                acc[0][g] = ffma2(a0, bb, acc[0][g]);
                acc[1][g] = ffma2(a1, bb, acc[1][g]);
            }
        }

        if (more) {
            float* An = As + (1 - cur) * 16 * LAST;
            float* Bn = Bs + (1 - cur) * 16 * LBST;
#pragma unroll
            for (int p = 0; p < 8; ++p) An[lk * LAST + lr + p * 8] = ra[p];
#pragma unroll
            for (int p = 0; p < 4; ++p) Bn[lk * LBST + lr + p * 8] = rbw[p];
        }
        __syncthreads();
    }

    const int hh = hh0 + j;
    if (hh < H) {
        const size_t H4 = (size_t)4 * H;
#pragma unroll
        for (int p = 0; p < 2; ++p) {
            float2 vi = unpack2(acc[p][0]);
            float2 vf = unpack2(acc[p][1]);
            float2 vg = unpack2(acc[p][2]);
            float2 vo = unpack2(acc[p][3]);
#pragma unroll
            for (int half = 0; half < 2; ++half) {
                int b = rowoff + rg * 4 + p * 2 + half;
                const float* xgb = xg_t + (size_t)b * H4 + hh;
                float pi = (half ? vi.y : vi.x) + xgb[0];
                float pf = (half ? vf.y : vf.x) + xgb[H];
                float pg = (half ? vg.y : vg.x) + xgb[2 * H];
                float po = (half ? vo.y : vo.x) + xgb[3 * H];
                float si = 1.0f / (1.0f + expf(-pi));
                float sf = 1.0f / (1.0f + expf(-pf));
                float so = 1.0f / (1.0f + expf(-po));
                float tg = tanhf(pg);
                size_t idx = (size_t)b * H + hh;
                float cc = sf * c_state[idx] + si * tg;
                c_state[idx] = cc;
                h_out[idx] = so * tanhf(cc);
            }
        }
    }
}

// ---------------------------------------------------------------------------
extern "C" void kernel_launch(void* const* d_in, const int* in_sizes, int n_in,
                              void* d_out, int out_size) {
    const int*   tokens = (const int*)d_in[0];
    const float* emb    = (const float*)d_in[1];
    const float* Wih[3] = {(const float*)d_in[2], (const float*)d_in[5], (const float*)d_in[8]};
    const float* Whh[3] = {(const float*)d_in[3], (const float*)d_in[6], (const float*)d_in[9]};
    const float* bb[3]  = {(const float*)d_in[4], (const float*)d_in[7], (const float*)d_in[10]};
    float* out = (float*)d_out;

    float *x0, *xg, *cst, *h0;
    cudaGetSymbolAddress((void**)&x0,  g_x0);
    cudaGetSymbolAddress((void**)&xg,  g_xg);
    cudaGetSymbolAddress((void**)&cst, g_c);
    cudaGetSymbolAddress((void**)&h0,  g_h0);

    cudaFuncSetAttribute(gemm_mma, cudaFuncAttributeMaxDynamicSharedMemorySize, DYN_SMEM);

    embed_kernel<<<MROWS, 128>>>(tokens, emb, x0);
    zero_kernel<<<(BATCH * 1150 + 255) / 256, 256>>>(h0, BATCH * 1150);

    const int Hs[3] = {1150, 1150, 400};
    const int Ks[3] = {400, 1150, 1150};
    const size_t outoff[3] = {0, (size_t)T_SEQ * BATCH * 1150, (size_t)T_SEQ * BATCH * 1150 * 2};

    const float* Ain = x0;
    for (int l = 0; l < 3; ++l) {
        const int H = Hs[l], K = Ks[l], N = 4 * H;

        zero_kernel<<<(BATCH * H + 255) / 256, 256>>>(cst, BATCH * H);

        dim3 grid((N + BN - 1) / BN, MROWS / BM);
        gemm_mma<<<grid, 256, DYN_SMEM>>>(Ain, Wih[l], bb[l], xg, MROWS, N, K);

        float* outl = out + outoff[l];
        dim3 sgrid((H + 7) / 8, 2);
        for (int t = 0; t < T_SEQ; ++t) {
            const float* hp = (t == 0) ? h0 : (outl + (size_t)(t - 1) * BATCH * H);
            lstm_step<<<sgrid, 128>>>(xg + (size_t)t * BATCH * N, hp,
                                      Whh[l], outl + (size_t)t * BATCH * H,
                                      cst, H);
        }
        Ain = outl;
    }
}

// round 5
// speedup vs baseline: 1.7233x; 1.7233x over previous
#include <cuda_runtime.h>
#include <cuda_fp16.h>
#include <math.h>
#include <stdint.h>

#define T_SEQ 200
#define BATCH 128
#define MROWS (T_SEQ * BATCH)   // 25600

// ---- device-global scratch ----
__device__ float g_x0[MROWS * 400];
__device__ float g_xg[(size_t)MROWS * 4600];
__device__ float g_c[BATCH * 1150];
__device__ __half g_wh[4 * 1150 * 1150];
__device__ __half g_wl[4 * 1150 * 1150];
__device__ __half g_hh[2][BATCH * 1150];
__device__ __half g_hl[2][BATCH * 1150];

// ---------------------------------------------------------------------------
__global__ void zero_kernel(float* __restrict__ p, int n) {
    int i = blockIdx.x * blockDim.x + threadIdx.x;
    if (i < n) p[i] = 0.0f;
}

__global__ void embed_kernel(const int* __restrict__ tokens,
                             const float* __restrict__ emb,
                             float* __restrict__ x) {
    int row = blockIdx.x;
    int tok = tokens[row];
    const float4* s = (const float4*)(emb + (size_t)tok * 400);
    float4* d = (float4*)(x + (size_t)row * 400);
    for (int i = threadIdx.x; i < 100; i += blockDim.x) d[i] = s[i];
}

// Pre-split + gate-permute W_hh: out row (4j+g) <- in row (g*H+j). K = H.
__global__ void whh_split(const float* __restrict__ W,
                          __half* __restrict__ hi, __half* __restrict__ lo,
                          int H) {
    int id = blockIdx.x * 256 + threadIdx.x;
    int total = 4 * H * H;
    if (id >= total) return;
    int r = id / H, k = id - r * H;
    int j = r >> 2, g = r & 3;
    float v = W[(size_t)(g * H + j) * H + k];
    __half h = __float2half_rn(v);
    hi[id] = h;
    lo[id] = __float2half_rn((v - __half2float(h)) * 2048.0f);
}

// ===========================================================================
// mma.sync fp16 + ldmatrix helpers (sm_80-era PTX, safe on plain sm_103)
// ===========================================================================
__device__ __forceinline__ uint32_t smem_u32(const void* p) {
    uint32_t a;
    asm("{ .reg .u64 t; cvta.to.shared.u64 t, %1; cvt.u32.u64 %0, t; }" : "=r"(a) : "l"(p));
    return a;
}
__device__ __forceinline__ void ldsm4(uint32_t* r, uint32_t a) {
    asm volatile("ldmatrix.sync.aligned.m8n8.x4.shared.b16 {%0,%1,%2,%3}, [%4];"
        : "=r"(r[0]), "=r"(r[1]), "=r"(r[2]), "=r"(r[3]) : "r"(a));
}
__device__ __forceinline__ void mma_h(float* d, const uint32_t* a, uint32_t b0, uint32_t b1) {
    asm volatile("mma.sync.aligned.m16n8k16.row.col.f32.f16.f16.f32 "
        "{%0,%1,%2,%3}, {%4,%5,%6,%7}, {%8,%9}, {%0,%1,%2,%3};"
        : "+f"(d[0]), "+f"(d[1]), "+f"(d[2]), "+f"(d[3])
        : "r"(a[0]), "r"(a[1]), "r"(a[2]), "r"(a[3]), "r"(b0), "r"(b1));
}
__device__ __forceinline__ void split2(float2 v, uint32_t& hi, uint32_t& lo) {
    __half hx = __float2half_rn(v.x), hy = __float2half_rn(v.y);
    __half lx = __float2half_rn((v.x - __half2float(hx)) * 2048.0f);
    __half ly = __float2half_rn((v.y - __half2float(hy)) * 2048.0f);
    hi = ((uint32_t)__half_as_ushort(hy) << 16) | (uint32_t)__half_as_ushort(hx);
    lo = ((uint32_t)__half_as_ushort(ly) << 16) | (uint32_t)__half_as_ushort(lx);
}
__device__ __forceinline__ float sigm(float x) { return 1.0f / (1.0f + expf(-x)); }

#define INV2048 (1.0f / 2048.0f)

extern __shared__ __half hsm[];

// ===========================================================================
// gemm_half: C[M,Ntot] = A[M,K] @ Wperm[Ntot,K]^T + biasperm
// W rows & bias permuted on load: phys row = (n&3)*H + (n>>2)  (gate interleave)
// CTA 128x64, 8 warps (warp 32x32), BK=32 fp32, double-buffered, ldmatrix.
// ===========================================================================
#define GROWS 40
#define G_AH 0
#define G_AL (128 * GROWS)          // 5120
#define G_BH (2 * 128 * GROWS)      // 10240
#define G_BL (G_BH + 64 * GROWS)    // 12800
#define G_STAGE (G_BH + 2 * 64 * GROWS)   // 15360 halves
#define G_SMEM (2 * G_STAGE * 2 + 256)    // bytes

__global__ __launch_bounds__(256) void gemm_half(
    const float* __restrict__ A, const float* __restrict__ W,
    const float* __restrict__ bias, float* __restrict__ C,
    int M, int Ntot, int K, int H)
{
    const int tid = threadIdx.x;
    const int lane = tid & 31, wid = tid >> 5;
    const int qt = lane & 3, qd = lane >> 2;
    const int n0 = blockIdx.x * 64;
    const int m0 = blockIdx.y * 128;
    const int wm = (wid >> 1) * 32, wn = (wid & 1) * 32;
    const uint32_t smb = smem_u32(hsm);

    float* bs = (float*)(hsm + 2 * G_STAGE);
    if (tid < 64) {
        int n = n0 + tid;
        bs[tid] = (n < Ntot) ? bias[(size_t)(n & 3) * H + (n >> 2)] : 0.0f;
    }

    float acc0[2][4][4] = {}, acc1[2][4][4] = {};
    float2 ra[8], rb[4];
    const int nt = (K + 31) / 32;

#define G_LDG(K0)                                                              \
    {                                                                          \
        _Pragma("unroll")                                                      \
        for (int it = 0; it < 8; ++it) {                                       \
            int g = tid + it * 256;                                            \
            int r = g >> 4, c2 = g & 15, k = (K0) + c2 * 2;                    \
            float2 v = make_float2(0.f, 0.f);                                  \
            const float* ap = A + (size_t)(m0 + r) * K + k;                    \
            if (k + 1 < K) v = *(const float2*)ap;                             \
            else if (k < K) v.x = *ap;                                         \
            ra[it] = v;                                                        \
        }                                                                      \
        _Pragma("unroll")                                                      \
        for (int it = 0; it < 4; ++it) {                                       \
            int g = tid + it * 256;                                            \
            int r = g >> 4, c2 = g & 15, k = (K0) + c2 * 2;                    \
            int n = n0 + r;                                                    \
            float2 v = make_float2(0.f, 0.f);                                  \
            if (n < Ntot) {                                                    \
                const float* wp = W + (size_t)((n & 3) * H + (n >> 2)) * K + k;\
                if (k + 1 < K) v = *(const float2*)wp;                         \
                else if (k < K) v.x = *wp;                                     \
            }                                                                  \
            rb[it] = v;                                                        \
        }                                                                      \
    }

#define G_STS(BUF)                                                             \
    {                                                                          \
        __half* st = hsm + (BUF) * G_STAGE;                                    \
        _Pragma("unroll")                                                      \
        for (int it = 0; it < 8; ++it) {                                       \
            int g = tid + it * 256;                                            \
            int r = g >> 4, c2 = g & 15;                                       \
            uint32_t hi, lo; split2(ra[it], hi, lo);                           \
            *(uint32_t*)(st + G_AH + r * GROWS + c2 * 2) = hi;                 \
            *(uint32_t*)(st + G_AL + r * GROWS + c2 * 2) = lo;                 \
        }                                                                      \
        _Pragma("unroll")                                                      \
        for (int it = 0; it < 4; ++it) {                                       \
            int g = tid + it * 256;                                            \
            int r = g >> 4, c2 = g & 15;                                       \
            uint32_t hi, lo; split2(rb[it], hi, lo);                           \
            *(uint32_t*)(st + G_BH + r * GROWS + c2 * 2) = hi;                 \
            *(uint32_t*)(st + G_BL + r * GROWS + c2 * 2) = lo;                 \
        }                                                                      \
    }

    G_LDG(0); G_STS(0);
    __syncthreads();

    for (int i = 0; i < nt; ++i) {
        const bool more = (i + 1 < nt);
        if (more) G_LDG((i + 1) * 32);
        const uint32_t sb = smb + (i & 1) * (G_STAGE * 2);
#pragma unroll
        for (int s = 0; s < 2; ++s) {
            const int k0 = s * 16;
            uint32_t ah[2][4], al[2][4];
#pragma unroll
            for (int mt = 0; mt < 2; ++mt) {
                uint32_t arow = wm + mt * 16 + (lane & 15);
                uint32_t acol = k0 + (lane >> 4) * 8;
                ldsm4(ah[mt], sb + 2 * (G_AH + arow * GROWS + acol));
                ldsm4(al[mt], sb + 2 * (G_AL + arow * GROWS + acol));
            }
            uint32_t bh[4][2], bl[4][2];
#pragma unroll
            for (int gp = 0; gp < 2; ++gp) {
                uint32_t brow = wn + gp * 16 + ((lane >> 4) & 1) * 8 + (lane & 7);
                uint32_t bcol = k0 + ((lane >> 3) & 1) * 8;
                uint32_t t[4];
                ldsm4(t, sb + 2 * (G_BH + brow * GROWS + bcol));
                bh[gp * 2][0] = t[0]; bh[gp * 2][1] = t[1];
                bh[gp * 2 + 1][0] = t[2]; bh[gp * 2 + 1][1] = t[3];
                ldsm4(t, sb + 2 * (G_BL + brow * GROWS + bcol));
                bl[gp * 2][0] = t[0]; bl[gp * 2][1] = t[1];
                bl[gp * 2 + 1][0] = t[2]; bl[gp * 2 + 1][1] = t[3];
            }
#pragma unroll
            for (int mt = 0; mt < 2; ++mt)
#pragma unroll
                for (int ntl = 0; ntl < 4; ++ntl) {
                    mma_h(acc0[mt][ntl], ah[mt], bh[ntl][0], bh[ntl][1]);
                    mma_h(acc1[mt][ntl], ah[mt], bl[ntl][0], bl[ntl][1]);
                    mma_h(acc1[mt][ntl], al[mt], bh[ntl][0], bh[ntl][1]);
                }
        }
        if (more) G_STS((i + 1) & 1);
        __syncthreads();
    }

#pragma unroll
    for (int mt = 0; mt < 2; ++mt) {
        int row = m0 + wm + mt * 16 + qd;
#pragma unroll
        for (int ntl = 0; ntl < 4; ++ntl) {
            int cl = wn + ntl * 8 + 2 * qt;
            int col = n0 + cl;
            if (col < Ntot) {
                float b0 = bs[cl], b1 = bs[cl + 1];
                float2 v0, v1;
                v0.x = acc0[mt][ntl][0] + acc1[mt][ntl][0] * INV2048 + b0;
                v0.y = acc0[mt][ntl][1] + acc1[mt][ntl][1] * INV2048 + b1;
                v1.x = acc0[mt][ntl][2] + acc1[mt][ntl][2] * INV2048 + b0;
                v1.y = acc0[mt][ntl][3] + acc1[mt][ntl][3] * INV2048 + b1;
                *(float2*)(C + (size_t)row * Ntot + col) = v0;
                *(float2*)(C + (size_t)(row + 8) * Ntot + col) = v1;
            }
        }
    }
}

// ===========================================================================
// lstm_mma: one timestep. g_pre = h_prev @ W_hh'^T (gate-interleaved N=4H),
// fused gate epilogue. CTA 128(m) x 32(n), 8 warps (warp 32x16). K = H.
// Inputs h planes (half hi/lo) from previous step; writes next h planes.
// ===========================================================================
#define LROWS 40
#define L_AH 0
#define L_AL (128 * LROWS)              // 5120
#define L_BH (2 * 128 * LROWS)          // 10240
#define L_BL (L_BH + 32 * LROWS)        // 11520
#define L_STAGE (L_BH + 2 * 32 * LROWS) // 12800 halves
#define L_SMEM (2 * L_STAGE * 2)        // 51200 bytes

__global__ __launch_bounds__(256) void lstm_mma(
    const float* __restrict__ xg_t,
    const __half* __restrict__ hHp, const __half* __restrict__ hLp,
    const __half* __restrict__ wHp, const __half* __restrict__ wLp,
    float* __restrict__ h_out, float* __restrict__ c_state,
    __half* __restrict__ hHn, __half* __restrict__ hLn,
    int H)
{
    const int Ntot = 4 * H, K = H;
    const int tid = threadIdx.x;
    const int lane = tid & 31, wid = tid >> 5;
    const int qt = lane & 3, qd = lane >> 2;
    const int n0 = blockIdx.x * 32;
    const int wm = (wid >> 1) * 32, wn = (wid & 1) * 16;
    const uint32_t smb = smem_u32(hsm);

    float acc0[2][2][4] = {}, acc1[2][2][4] = {};
    uint32_t raH[8], raL[8], rbH[2], rbL[2];
    const int nt = (K + 31) / 32;

#define L_LDG(K0)                                                              \
    {                                                                          \
        _Pragma("unroll")                                                      \
        for (int it = 0; it < 8; ++it) {                                       \
            int g = tid + it * 256;                                            \
            int r = g >> 4, c2 = g & 15, k = (K0) + c2 * 2;                    \
            if (k + 1 < K) {                                                   \
                raH[it] = *(const uint32_t*)(hHp + (size_t)r * K + k);         \
                raL[it] = *(const uint32_t*)(hLp + (size_t)r * K + k);         \
            } else if (k < K) {                                                \
                raH[it] = (uint32_t)__half_as_ushort(hHp[(size_t)r * K + k]);  \
                raL[it] = (uint32_t)__half_as_ushort(hLp[(size_t)r * K + k]);  \
            } else { raH[it] = 0u; raL[it] = 0u; }                             \
        }                                                                      \
        _Pragma("unroll")                                                      \
        for (int it = 0; it < 2; ++it) {                                       \
            int g = tid + it * 256;                                            \
            int r = g >> 4, c2 = g & 15, k = (K0) + c2 * 2;                    \
            int n = n0 + r;                                                    \
            rbH[it] = 0u; rbL[it] = 0u;                                        \
            if (n < Ntot) {                                                    \
                if (k + 1 < K) {                                               \
                    rbH[it] = *(const uint32_t*)(wHp + (size_t)n * K + k);     \
                    rbL[it] = *(const uint32_t*)(wLp + (size_t)n * K + k);     \
                } else if (k < K) {                                            \
                    rbH[it] = (uint32_t)__half_as_ushort(wHp[(size_t)n * K + k]); \
                    rbL[it] = (uint32_t)__half_as_ushort(wLp[(size_t)n * K + k]); \
                }                                                              \
            }                                                                  \
        }                                                                      \
    }

#define L_STS(BUF)                                                             \
    {                                                                          \
        __half* st = hsm + (BUF) * L_STAGE;                                    \
        _Pragma("unroll")                                                      \
        for (int it = 0; it < 8; ++it) {                                       \
            int g = tid + it * 256;                                            \
            int r = g >> 4, c2 = g & 15;                                       \
            *(uint32_t*)(st + L_AH + r * LROWS + c2 * 2) = raH[it];            \
            *(uint32_t*)(st + L_AL + r * LROWS + c2 * 2) = raL[it];            \
        }                                                                      \
        _Pragma("unroll")                                                      \
        for (int it = 0; it < 2; ++it) {                                       \
            int g = tid + it * 256;                                            \
            int r = g >> 4, c2 = g & 15;                                       \
            *(uint32_t*)(st + L_BH + r * LROWS + c2 * 2) = rbH[it];            \
            *(uint32_t*)(st + L_BL + r * LROWS + c2 * 2) = rbL[it];            \
        }                                                                      \
    }

    L_LDG(0); L_STS(0);
    __syncthreads();

    for (int i = 0; i < nt; ++i) {
        const bool more = (i + 1 < nt);
        if (more) L_LDG((i + 1) * 32);
        const uint32_t sb = smb + (i & 1) * (L_STAGE * 2);
#pragma unroll
        for (int s = 0; s < 2; ++s) {
            const int k0 = s * 16;
            uint32_t ah[2][4], al[2][4];
#pragma unroll
            for (int mt = 0; mt < 2; ++mt) {
                uint32_t arow = wm + mt * 16 + (lane & 15);
                uint32_t acol = k0 + (lane >> 4) * 8;
                ldsm4(ah[mt], sb + 2 * (L_AH + arow * LROWS + acol));
                ldsm4(al[mt], sb + 2 * (L_AL + arow * LROWS + acol));
            }
            uint32_t bh[2][2], bl[2][2];
            {
                uint32_t brow = wn + ((lane >> 4) & 1) * 8 + (lane & 7);
                uint32_t bcol = k0 + ((lane >> 3) & 1) * 8;
                uint32_t t[4];
                ldsm4(t, sb + 2 * (L_BH + brow * LROWS + bcol));
                bh[0][0] = t[0]; bh[0][1] = t[1]; bh[1][0] = t[2]; bh[1][1] = t[3];
                ldsm4(t, sb + 2 * (L_BL + brow * LROWS + bcol));
                bl[0][0] = t[0]; bl[0][1] = t[1]; bl[1][0] = t[2]; bl[1][1] = t[3];
            }
#pragma unroll
            for (int mt = 0; mt < 2; ++mt)
#pragma unroll
                for (int ntl = 0; ntl < 2; ++ntl) {
                    mma_h(acc0[mt][ntl], ah[mt], bh[ntl][0], bh[ntl][1]);
                    mma_h(acc1[mt][ntl], ah[mt], bl[ntl][0], bl[ntl][1]);
                    mma_h(acc1[mt][ntl], al[mt], bh[ntl][0], bh[ntl][1]);
                }
        }
        if (more) L_STS((i + 1) & 1);
        __syncthreads();
    }

    // ---- fused gate epilogue ----
    __syncthreads();                       // stages dead; overlay gate smem
    float* gsm = (float*)hsm + wid * (32 * 20);
#pragma unroll
    for (int mt = 0; mt < 2; ++mt)
#pragma unroll
        for (int ntl = 0; ntl < 2; ++ntl) {
            int r0 = mt * 16 + qd;
            int c0 = ntl * 8 + 2 * qt;
            gsm[r0 * 20 + c0]           = acc0[mt][ntl][0] + acc1[mt][ntl][0] * INV2048;
            gsm[r0 * 20 + c0 + 1]       = acc0[mt][ntl][1] + acc1[mt][ntl][1] * INV2048;
            gsm[(r0 + 8) * 20 + c0]     = acc0[mt][ntl][2] + acc1[mt][ntl][2] * INV2048;
            gsm[(r0 + 8) * 20 + c0 + 1] = acc0[mt][ntl][3] + acc1[mt][ntl][3] * INV2048;
        }
    __syncwarp();

    const int b = wm + lane;               // this lane's batch row
    const int nbase = n0 + wn;
#pragma unroll
    for (int u = 0; u < 4; ++u) {
        int colg = nbase + 4 * u;
        if (colg < Ntot) {
            int j = colg >> 2;             // hidden unit
            float4 g4 = *(float4*)&gsm[lane * 20 + 4 * u];
            float4 x4 = *(const float4*)(xg_t + (size_t)b * Ntot + colg);
            float pi = g4.x + x4.x;
            float pf = g4.y + x4.y;
            float pg = g4.z + x4.z;
            float po = g4.w + x4.w;
            size_t idx = (size_t)b * H + j;
            float cc = sigm(pf) * c_state[idx] + sigm(pi) * tanhf(pg);
            c_state[idx] = cc;
            float h = sigm(po) * tanhf(cc);
            h_out[idx] = h;
            __half hh = __float2half_rn(h);
            hHn[idx] = hh;
            hLn[idx] = __float2half_rn((h - __half2float(hh)) * 2048.0f);
        }
    }
}

// ---------------------------------------------------------------------------
extern "C" void kernel_launch(void* const* d_in, const int* in_sizes, int n_in,
                              void* d_out, int out_size) {
    const int*   tokens = (const int*)d_in[0];
    const float* emb    = (const float*)d_in[1];
    const float* Wih[3] = {(const float*)d_in[2], (const float*)d_in[5], (const float*)d_in[8]};
    const float* Whh[3] = {(const float*)d_in[3], (const float*)d_in[6], (const float*)d_in[9]};
    const float* bb[3]  = {(const float*)d_in[4], (const float*)d_in[7], (const float*)d_in[10]};
    float* out = (float*)d_out;

    float *x0, *xg, *cst;
    __half *wh, *wl, *hh0, *hh1, *hl0, *hl1;
    cudaGetSymbolAddress((void**)&x0,  g_x0);
    cudaGetSymbolAddress((void**)&xg,  g_xg);
    cudaGetSymbolAddress((void**)&cst, g_c);
    cudaGetSymbolAddress((void**)&wh,  g_wh);
    cudaGetSymbolAddress((void**)&wl,  g_wl);
    cudaGetSymbolAddress((void**)&hh0, g_hh);  hh1 = hh0 + BATCH * 1150;
    cudaGetSymbolAddress((void**)&hl0, g_hl);  hl1 = hl0 + BATCH * 1150;
    __half* hhp[2] = {hh0, hh1};
    __half* hlp[2] = {hl0, hl1};

    cudaFuncSetAttribute(gemm_half, cudaFuncAttributeMaxDynamicSharedMemorySize, G_SMEM);
    cudaFuncSetAttribute(lstm_mma,  cudaFuncAttributeMaxDynamicSharedMemorySize, L_SMEM);

    embed_kernel<<<MROWS, 128>>>(tokens, emb, x0);

    const int Hs[3] = {1150, 1150, 400};
    const int Ks[3] = {400, 1150, 1150};
    const size_t outoff[3] = {0, (size_t)T_SEQ * BATCH * 1150, (size_t)T_SEQ * BATCH * 1150 * 2};

    const float* Ain = x0;
    for (int l = 0; l < 3; ++l) {
        const int H = Hs[l], K = Ks[l], N = 4 * H;

        whh_split<<<(4 * H * H + 255) / 256, 256>>>(Whh[l], wh, wl, H);
        zero_kernel<<<(BATCH * H + 255) / 256, 256>>>(cst, BATCH * H);
        zero_kernel<<<(BATCH * H / 2 + 255) / 256, 256>>>((float*)hhp[0], BATCH * H / 2);
        zero_kernel<<<(BATCH * H / 2 + 255) / 256, 256>>>((float*)hlp[0], BATCH * H / 2);

        dim3 grid((N + 63) / 64, MROWS / 128);
        gemm_half<<<grid, 256, G_SMEM>>>(Ain, Wih[l], bb[l], xg, MROWS, N, K, H);

        float* outl = out + outoff[l];
        const int nblk = (N + 31) / 32;
        for (int t = 0; t < T_SEQ; ++t) {
            lstm_mma<<<nblk, 256, L_SMEM>>>(
                xg + (size_t)t * BATCH * N,
                hhp[t & 1], hlp[t & 1], wh, wl,
                outl + (size_t)t * BATCH * H, cst,
                hhp[(t + 1) & 1], hlp[(t + 1) & 1], H);
        }
        Ain = outl;
    }
}

// round 6
// speedup vs baseline: 2.1366x; 1.2399x over previous
#include <cuda_runtime.h>
#include <cuda_fp16.h>
#include <math.h>
#include <stdint.h>

#define T_SEQ 200
#define BATCH 128
#define MROWS (T_SEQ * BATCH)   // 25600
#define INV2048 (1.0f / 2048.0f)

// ---- device-global scratch ----
__device__ float  g_xg[(size_t)MROWS * 4600];
__device__ float  g_c[BATCH * 1150];
__device__ __half g_ah[(size_t)(T_SEQ + 1) * BATCH * 1152];  // A planes / h planes
__device__ __half g_al[(size_t)(T_SEQ + 1) * BATCH * 1152];
__device__ __half g_wbh[(size_t)4608 * 1152];                // weight planes (shared W_ih/W_hh)
__device__ __half g_wbl[(size_t)4608 * 1152];

// ===========================================================================
// PTX helpers (sm_80-era, safe on plain sm_103 target)
// ===========================================================================
__device__ __forceinline__ uint32_t smem_u32(const void* p) {
    uint32_t a;
    asm("{ .reg .u64 t; cvta.to.shared.u64 t, %1; cvt.u32.u64 %0, t; }" : "=r"(a) : "l"(p));
    return a;
}
__device__ __forceinline__ void cp16(uint32_t s, const void* g) {
    asm volatile("cp.async.cg.shared.global [%0], [%1], 16;" :: "r"(s), "l"(g));
}
__device__ __forceinline__ void cp_commit() {
    asm volatile("cp.async.commit_group;");
}
template <int N> __device__ __forceinline__ void cp_wait() {
    asm volatile("cp.async.wait_group %0;" :: "n"(N));
}
__device__ __forceinline__ void ldsm4(uint32_t* r, uint32_t a) {
    asm volatile("ldmatrix.sync.aligned.m8n8.x4.shared.b16 {%0,%1,%2,%3}, [%4];"
        : "=r"(r[0]), "=r"(r[1]), "=r"(r[2]), "=r"(r[3]) : "r"(a));
}
__device__ __forceinline__ void mma_h(float* d, const uint32_t* a, uint32_t b0, uint32_t b1) {
    asm volatile("mma.sync.aligned.m16n8k16.row.col.f32.f16.f16.f32 "
        "{%0,%1,%2,%3}, {%4,%5,%6,%7}, {%8,%9}, {%0,%1,%2,%3};"
        : "+f"(d[0]), "+f"(d[1]), "+f"(d[2]), "+f"(d[3])
        : "r"(a[0]), "r"(a[1]), "r"(a[2]), "r"(a[3]), "r"(b0), "r"(b1));
}
__device__ __forceinline__ float sigm(float x) { return 1.0f / (1.0f + expf(-x)); }

// ===========================================================================
// Pre-split kernels
// ===========================================================================
__global__ void embed_split(const int* __restrict__ tokens,
                            const float* __restrict__ emb,
                            __half* __restrict__ ah, __half* __restrict__ al) {
    int row = blockIdx.x;
    int tok = tokens[row];
    const float* src = emb + (size_t)tok * 400;
    __half* dh = ah + (size_t)row * 416;
    __half* dl = al + (size_t)row * 416;
    for (int i = threadIdx.x; i < 416; i += blockDim.x) {
        float v = (i < 400) ? src[i] : 0.0f;
        __half h = __float2half_rn(v);
        dh[i] = h;
        dl[i] = __float2half_rn((v - __half2float(h)) * 2048.0f);
    }
}

// split + gate-permute weights: out row n = (4j+g) <- src row (g*H+j); zero-pad k>=K
__global__ void split_w(const float* __restrict__ W,
                        __half* __restrict__ bh, __half* __restrict__ bl,
                        int H, int K, int KP) {
    int id = blockIdx.x * 256 + threadIdx.x;
    int total = 4 * H * KP;
    if (id >= total) return;
    int n = id / KP, k = id - n * KP;
    float v = (k < K) ? W[(size_t)((n & 3) * H + (n >> 2)) * K + k] : 0.0f;
    __half h = __float2half_rn(v);
    bh[id] = h;
    bl[id] = __float2half_rn((v - __half2float(h)) * 2048.0f);
}

// ===========================================================================
// gemm_half: xg[M,Ntot] = A[M,K] @ Wperm[Ntot,K]^T + biasperm
// Pre-split half planes in gmem. CTA 128x128, 8 warps (32x64), cp.async 3-stage.
// Stage layout (halves): AH[128][40] | AL | BH[128][40] | BL
// ===========================================================================
#define GS 3
#define G_STG 20480
#define GEMM_SMEM (GS * G_STG * 2 + 512)

__device__ __forceinline__ void g_load(uint32_t smb, int stage,
    const __half* __restrict__ Ah, const __half* __restrict__ Al,
    const __half* __restrict__ Bh, const __half* __restrict__ Bl,
    int m0, int n0, int KP, int k0, int tid)
{
#pragma unroll
    for (int it = 0; it < 4; ++it) {
        int g = tid + it * 256;
        int pl = g >> 9, r = (g >> 2) & 127, cg = g & 3;
        const __half* src = (pl ? Al : Ah) + (size_t)(m0 + r) * KP + k0 + cg * 8;
        cp16(smb + 2 * (stage * G_STG + pl * 5120 + r * 40 + cg * 8), src);
    }
#pragma unroll
    for (int it = 0; it < 4; ++it) {
        int g = tid + it * 256;
        int pl = g >> 9, r = (g >> 2) & 127, cg = g & 3;
        const __half* src = (pl ? Bl : Bh) + (size_t)(n0 + r) * KP + k0 + cg * 8;
        cp16(smb + 2 * (stage * G_STG + 10240 + pl * 5120 + r * 40 + cg * 8), src);
    }
}

extern __shared__ __half hsm[];

__global__ __launch_bounds__(256) void gemm_half(
    const __half* __restrict__ Ah, const __half* __restrict__ Al,
    const __half* __restrict__ Bh, const __half* __restrict__ Bl,
    const float* __restrict__ bias, float* __restrict__ C,
    int Ntot, int KP, int H)
{
    const int tid = threadIdx.x;
    const int lane = tid & 31, wid = tid >> 5;
    const int qt = lane & 3, qd = lane >> 2;
    const int n0 = blockIdx.x * 128;
    const int m0 = blockIdx.y * 128;
    const int wm = (wid >> 1) * 32, wn = (wid & 1) * 64;
    const uint32_t smb = smem_u32(hsm);

    float* bs = (float*)(hsm + GS * G_STG);
    if (tid < 128) {
        int n = n0 + tid;
        bs[tid] = (n < Ntot) ? bias[(size_t)(n & 3) * H + (n >> 2)] : 0.0f;
    }

    float acc0[2][8][4] = {}, acc1[2][8][4] = {};
    const int nt = KP / 32;

    // prologue: stages 0..GS-2
#pragma unroll
    for (int s = 0; s < GS - 1; ++s) {
        g_load(smb, s, Ah, Al, Bh, Bl, m0, n0, KP, s * 32, tid);
        cp_commit();
    }

    for (int i = 0; i < nt; ++i) {
        if (i + GS - 1 < nt)
            g_load(smb, (i + GS - 1) % GS, Ah, Al, Bh, Bl, m0, n0, KP, (i + GS - 1) * 32, tid);
        cp_commit();
        cp_wait<GS - 1>();
        __syncthreads();

        const uint32_t sb = smb + 2 * ((i % GS) * G_STG);
#pragma unroll
        for (int s = 0; s < 2; ++s) {
            const int k0 = s * 16;
            uint32_t afh[2][4], afl[2][4];
#pragma unroll
            for (int mt = 0; mt < 2; ++mt) {
                uint32_t arow = wm + mt * 16 + (lane & 15);
                uint32_t acol = k0 + (lane >> 4) * 8;
                ldsm4(afh[mt], sb + 2 * (arow * 40 + acol));
                ldsm4(afl[mt], sb + 2 * (5120u + arow * 40 + acol));
            }
#pragma unroll
            for (int gp = 0; gp < 4; ++gp) {
                uint32_t brow = wn + gp * 16 + ((lane >> 4) & 1) * 8 + (lane & 7);
                uint32_t bcol = k0 + ((lane >> 3) & 1) * 8;
                uint32_t tb[4], tl[4];
                ldsm4(tb, sb + 2 * (10240u + brow * 40 + bcol));
                ldsm4(tl, sb + 2 * (15360u + brow * 40 + bcol));
#pragma unroll
                for (int mt = 0; mt < 2; ++mt)
#pragma unroll
                    for (int j = 0; j < 2; ++j) {
                        int ntl = gp * 2 + j;
                        mma_h(acc0[mt][ntl], afh[mt], tb[j * 2], tb[j * 2 + 1]);
                        mma_h(acc1[mt][ntl], afh[mt], tl[j * 2], tl[j * 2 + 1]);
                        mma_h(acc1[mt][ntl], afl[mt], tb[j * 2], tb[j * 2 + 1]);
                    }
            }
        }
        __syncthreads();
    }

#pragma unroll
    for (int mt = 0; mt < 2; ++mt) {
        int row = m0 + wm + mt * 16 + qd;
#pragma unroll
        for (int ntl = 0; ntl < 8; ++ntl) {
            int cl = wn + ntl * 8 + 2 * qt;
            int col = n0 + cl;
            if (col < Ntot) {
                float b0 = bs[cl], b1 = bs[cl + 1];
                float2 v0, v1;
                v0.x = acc0[mt][ntl][0] + acc1[mt][ntl][0] * INV2048 + b0;
                v0.y = acc0[mt][ntl][1] + acc1[mt][ntl][1] * INV2048 + b1;
                v1.x = acc0[mt][ntl][2] + acc1[mt][ntl][2] * INV2048 + b0;
                v1.y = acc0[mt][ntl][3] + acc1[mt][ntl][3] * INV2048 + b1;
                *(float2*)(C + (size_t)row * Ntot + col) = v0;
                *(float2*)(C + (size_t)(row + 8) * Ntot + col) = v1;
            }
        }
    }
}

// ===========================================================================
// lstm_mma<NT>: one timestep. Gate pre-acts = h_prev @ Whh'^T (+xg), fused gates.
// NT=32: 256 thr, 8 warps (warp 32x16), grid 144.  NT=16: 128 thr, 4 warps, grid 100.
// 4-stage cp.async. Stage: AH[128][40] | AL | BH[NT][40] | BL
// ===========================================================================
#define LS 4

template <int NT>
__global__ __launch_bounds__(NT == 32 ? 256 : 128) void lstm_mma(
    const float* __restrict__ xg_t,
    const __half* __restrict__ hH, const __half* __restrict__ hL,
    const __half* __restrict__ wH, const __half* __restrict__ wL,
    float* __restrict__ h_out, float* __restrict__ c_state,
    __half* __restrict__ nH, __half* __restrict__ nL,
    int H, int KP)
{
    constexpr int T = (NT == 32) ? 256 : 128;
    constexpr int L_STG = 10240 + 2 * NT * 40;
    constexpr int BOFF = 10240;
    const int Ntot = 4 * H;
    const int tid = threadIdx.x;
    const int lane = tid & 31, wid = tid >> 5;
    const int qt = lane & 3, qd = lane >> 2;
    const int n0 = blockIdx.x * NT;
    const int wm = (NT == 32) ? (wid >> 1) * 32 : wid * 32;
    const int wn = (NT == 32) ? (wid & 1) * 16 : 0;
    const uint32_t smb = smem_u32(hsm);

    float acc0[2][2][4] = {}, acc1[2][2][4] = {};
    const int nt = KP / 32;

#define L_LOAD(STAGE, K0)                                                     \
    {                                                                         \
        _Pragma("unroll")                                                     \
        for (int it = 0; it < 1024 / T; ++it) {                               \
            int g = tid + it * T;                                             \
            int pl = g >> 9, r = (g >> 2) & 127, cg = g & 3;                  \
            const __half* src = (pl ? hL : hH) + (size_t)r * KP + (K0) + cg * 8; \
            cp16(smb + 2 * ((STAGE) * L_STG + pl * 5120 + r * 40 + cg * 8), src); \
        }                                                                     \
        {                                                                     \
            int g = tid;                                                      \
            int pl = g / (NT * 4), rr = (g >> 2) % NT, cg = g & 3;            \
            const __half* src = (pl ? wL : wH) + (size_t)(n0 + rr) * KP + (K0) + cg * 8; \
            cp16(smb + 2 * ((STAGE) * L_STG + BOFF + pl * NT * 40 + rr * 40 + cg * 8), src); \
        }                                                                     \
    }

#pragma unroll
    for (int s = 0; s < LS - 1; ++s) {
        L_LOAD(s, s * 32);
        cp_commit();
    }

    for (int i = 0; i < nt; ++i) {
        if (i + LS - 1 < nt) L_LOAD((i + LS - 1) % LS, (i + LS - 1) * 32);
        cp_commit();
        cp_wait<LS - 1>();
        __syncthreads();

        const uint32_t sb = smb + 2 * ((i % LS) * L_STG);
#pragma unroll
        for (int s = 0; s < 2; ++s) {
            const int k0 = s * 16;
            uint32_t afh[2][4], afl[2][4];
#pragma unroll
            for (int mt = 0; mt < 2; ++mt) {
                uint32_t arow = wm + mt * 16 + (lane & 15);
                uint32_t acol = k0 + (lane >> 4) * 8;
                ldsm4(afh[mt], sb + 2 * (arow * 40 + acol));
                ldsm4(afl[mt], sb + 2 * (5120u + arow * 40 + acol));
            }
            uint32_t bh[2][2], bl[2][2];
            {
                uint32_t brow = wn + ((lane >> 4) & 1) * 8 + (lane & 7);
                uint32_t bcol = k0 + ((lane >> 3) & 1) * 8;
                uint32_t t4[4];
                ldsm4(t4, sb + 2 * (BOFF + brow * 40 + bcol));
                bh[0][0] = t4[0]; bh[0][1] = t4[1]; bh[1][0] = t4[2]; bh[1][1] = t4[3];
                ldsm4(t4, sb + 2 * (BOFF + NT * 40 + brow * 40 + bcol));
                bl[0][0] = t4[0]; bl[0][1] = t4[1]; bl[1][0] = t4[2]; bl[1][1] = t4[3];
            }
#pragma unroll
            for (int mt = 0; mt < 2; ++mt)
#pragma unroll
                for (int ntl = 0; ntl < 2; ++ntl) {
                    mma_h(acc0[mt][ntl], afh[mt], bh[ntl][0], bh[ntl][1]);
                    mma_h(acc1[mt][ntl], afh[mt], bl[ntl][0], bl[ntl][1]);
                    mma_h(acc1[mt][ntl], afl[mt], bh[ntl][0], bh[ntl][1]);
                }
        }
        __syncthreads();
    }

    // ---- fused gate epilogue (overlay gate smem on dead stage region) ----
    float* gsm = (float*)hsm + wid * (32 * 20);
#pragma unroll
    for (int mt = 0; mt < 2; ++mt)
#pragma unroll
        for (int ntl = 0; ntl < 2; ++ntl) {
            int r0 = mt * 16 + qd;
            int c0 = ntl * 8 + 2 * qt;
            gsm[r0 * 20 + c0]           = acc0[mt][ntl][0] + acc1[mt][ntl][0] * INV2048;
            gsm[r0 * 20 + c0 + 1]       = acc0[mt][ntl][1] + acc1[mt][ntl][1] * INV2048;
            gsm[(r0 + 8) * 20 + c0]     = acc0[mt][ntl][2] + acc1[mt][ntl][2] * INV2048;
            gsm[(r0 + 8) * 20 + c0 + 1] = acc0[mt][ntl][3] + acc1[mt][ntl][3] * INV2048;
        }
    __syncwarp();

    const int b = wm + lane;
    const int nbase = n0 + wn;
#pragma unroll
    for (int u = 0; u < 4; ++u) {
        int colg = nbase + 4 * u;
        if (colg < Ntot) {
            int j = colg >> 2;
            float4 g4 = *(float4*)&gsm[lane * 20 + 4 * u];
            float4 x4 = *(const float4*)(xg_t + (size_t)b * Ntot + colg);
            float pi = g4.x + x4.x;
            float pf = g4.y + x4.y;
            float pg = g4.z + x4.z;
            float po = g4.w + x4.w;
            size_t idx = (size_t)b * H + j;
            float cc = sigm(pf) * c_state[idx] + sigm(pi) * tanhf(pg);
            c_state[idx] = cc;
            float h = sigm(po) * tanhf(cc);
            h_out[idx] = h;
            __half hh = __float2half_rn(h);
            size_t pidx = (size_t)b * KP + j;
            nH[pidx] = hh;
            nL[pidx] = __float2half_rn((h - __half2float(hh)) * 2048.0f);
        }
    }
}

// ---------------------------------------------------------------------------
extern "C" void kernel_launch(void* const* d_in, const int* in_sizes, int n_in,
                              void* d_out, int out_size) {
    const int*   tokens = (const int*)d_in[0];
    const float* emb    = (const float*)d_in[1];
    const float* Wih[3] = {(const float*)d_in[2], (const float*)d_in[5], (const float*)d_in[8]};
    const float* Whh[3] = {(const float*)d_in[3], (const float*)d_in[6], (const float*)d_in[9]};
    const float* bb[3]  = {(const float*)d_in[4], (const float*)d_in[7], (const float*)d_in[10]};
    float* out = (float*)d_out;

    float *xg, *cst;
    __half *ah, *al, *wbh, *wbl;
    cudaGetSymbolAddress((void**)&xg,  g_xg);
    cudaGetSymbolAddress((void**)&cst, g_c);
    cudaGetSymbolAddress((void**)&ah,  g_ah);
    cudaGetSymbolAddress((void**)&al,  g_al);
    cudaGetSymbolAddress((void**)&wbh, g_wbh);
    cudaGetSymbolAddress((void**)&wbl, g_wbl);

    const int LSTM32_SMEM = LS * (10240 + 2 * 32 * 40) * 2;  // 102400
    const int LSTM16_SMEM = LS * (10240 + 2 * 16 * 40) * 2;  // 92160
    cudaFuncSetAttribute(gemm_half,    cudaFuncAttributeMaxDynamicSharedMemorySize, GEMM_SMEM);
    cudaFuncSetAttribute(lstm_mma<32>, cudaFuncAttributeMaxDynamicSharedMemorySize, LSTM32_SMEM);
    cudaFuncSetAttribute(lstm_mma<16>, cudaFuncAttributeMaxDynamicSharedMemorySize, LSTM16_SMEM);

    // embedding -> split planes (stride 416, zero-padded)
    embed_split<<<MROWS, 128>>>(tokens, emb, ah, al);

    const int Hs[3]   = {1150, 1150, 400};
    const int Kin[3]  = {400, 1150, 1150};
    const int KPin[3] = {416, 1152, 1152};
    const int HPs[3]  = {1152, 1152, 416};
    const size_t outoff[3] = {0, (size_t)MROWS * 1150, (size_t)MROWS * 1150 * 2};

    for (int l = 0; l < 3; ++l) {
        const int H = Hs[l], K = Kin[l], KP = KPin[l], HP = HPs[l], N = 4 * H;

        // input-weight planes + GEMM for xg
        split_w<<<(4 * H * KP + 255) / 256, 256>>>(Wih[l], wbh, wbl, H, K, KP);
        const __half* Asrc_h = (l == 0) ? ah : (ah + (size_t)BATCH * 1152);
        const __half* Asrc_l = (l == 0) ? al : (al + (size_t)BATCH * 1152);
        dim3 gg((N + 127) / 128, MROWS / 128);
        gemm_half<<<gg, 256, GEMM_SMEM>>>(Asrc_h, Asrc_l, wbh, wbl, bb[l], xg, N, KP, H);

        // reset h-plane buffer (also zeroes slot 0 and pads) + cell state
        cudaMemsetAsync(ah, 0, (size_t)(T_SEQ + 1) * BATCH * HP * 2);
        cudaMemsetAsync(al, 0, (size_t)(T_SEQ + 1) * BATCH * HP * 2);
        cudaMemsetAsync(cst, 0, (size_t)BATCH * H * 4);

        // recurrent-weight planes
        split_w<<<(4 * H * HP + 255) / 256, 256>>>(Whh[l], wbh, wbl, H, H, HP);

        float* outl = out + outoff[l];
        for (int t = 0; t < T_SEQ; ++t) {
            const __half* hHp = ah + (size_t)t * BATCH * HP;
            const __half* hLp = al + (size_t)t * BATCH * HP;
            __half* nHp = ah + (size_t)(t + 1) * BATCH * HP;
            __half* nLp = al + (size_t)(t + 1) * BATCH * HP;
            const float* xgt = xg + (size_t)t * BATCH * N;
            float* ho = outl + (size_t)t * BATCH * H;
            if (H == 1150) {
                lstm_mma<32><<<(N + 31) / 32, 256, LSTM32_SMEM>>>(
                    xgt, hHp, hLp, wbh, wbl, ho, cst, nHp, nLp, H, HP);
            } else {
                lstm_mma<16><<<(N + 15) / 16, 128, LSTM16_SMEM>>>(
                    xgt, hHp, hLp, wbh, wbl, ho, cst, nHp, nLp, H, HP);
            }
        }
    }
}

// round 7
// speedup vs baseline: 2.6506x; 1.2406x over previous
#include <cuda_runtime.h>
#include <cuda_fp16.h>
#include <math.h>
#include <stdint.h>

#define T_SEQ 200
#define BATCH 128
#define MROWS (T_SEQ * BATCH)   // 25600
#define INV2048 (1.0f / 2048.0f)

// ---- device-global scratch ----
__device__ float  g_xg[(size_t)MROWS * 4600];
__device__ __half g_ah[(size_t)(T_SEQ + 1) * BATCH * 1152];  // A planes / h planes
__device__ __half g_al[(size_t)(T_SEQ + 1) * BATCH * 1152];
__device__ __half g_wbh[(size_t)4608 * 1152];                // weight planes
__device__ __half g_wbl[(size_t)4608 * 1152];
__device__ unsigned g_ctr[4];                                // grid-barrier counters

// ===========================================================================
// PTX helpers (sm_80-era, safe on plain sm_103 target)
// ===========================================================================
__device__ __forceinline__ uint32_t smem_u32(const void* p) {
    uint32_t a;
    asm("{ .reg .u64 t; cvta.to.shared.u64 t, %1; cvt.u32.u64 %0, t; }" : "=r"(a) : "l"(p));
    return a;
}
__device__ __forceinline__ void cp16(uint32_t s, const void* g) {
    asm volatile("cp.async.cg.shared.global [%0], [%1], 16;" :: "r"(s), "l"(g));
}
__device__ __forceinline__ void cp_commit() {
    asm volatile("cp.async.commit_group;");
}
template <int N> __device__ __forceinline__ void cp_wait() {
    asm volatile("cp.async.wait_group %0;" :: "n"(N));
}
__device__ __forceinline__ void ldsm4(uint32_t* r, uint32_t a) {
    asm volatile("ldmatrix.sync.aligned.m8n8.x4.shared.b16 {%0,%1,%2,%3}, [%4];"
        : "=r"(r[0]), "=r"(r[1]), "=r"(r[2]), "=r"(r[3]) : "r"(a));
}
__device__ __forceinline__ void mma_h(float* d, const uint32_t* a, uint32_t b0, uint32_t b1) {
    asm volatile("mma.sync.aligned.m16n8k16.row.col.f32.f16.f16.f32 "
        "{%0,%1,%2,%3}, {%4,%5,%6,%7}, {%8,%9}, {%0,%1,%2,%3};"
        : "+f"(d[0]), "+f"(d[1]), "+f"(d[2]), "+f"(d[3])
        : "r"(a[0]), "r"(a[1]), "r"(a[2]), "r"(a[3]), "r"(b0), "r"(b1));
}
__device__ __forceinline__ float sigm(float x) { return 1.0f / (1.0f + expf(-x)); }

// ===========================================================================
// Pre-split kernels
// ===========================================================================
__global__ void embed_split(const int* __restrict__ tokens,
                            const float* __restrict__ emb,
                            __half* __restrict__ ah, __half* __restrict__ al) {
    int row = blockIdx.x;
    int tok = tokens[row];
    const float* src = emb + (size_t)tok * 400;
    __half* dh = ah + (size_t)row * 416;
    __half* dl = al + (size_t)row * 416;
    for (int i = threadIdx.x; i < 416; i += blockDim.x) {
        float v = (i < 400) ? src[i] : 0.0f;
        __half h = __float2half_rn(v);
        dh[i] = h;
        dl[i] = __float2half_rn((v - __half2float(h)) * 2048.0f);
    }
}

// split + gate-permute weights: out row n = (4j+g) <- src row (g*H+j); zero-pad k>=K
__global__ void split_w(const float* __restrict__ W,
                        __half* __restrict__ bh, __half* __restrict__ bl,
                        int H, int K, int KP) {
    int id = blockIdx.x * 256 + threadIdx.x;
    int total = 4 * H * KP;
    if (id >= total) return;
    int n = id / KP, k = id - n * KP;
    float v = (k < K) ? W[(size_t)((n & 3) * H + (n >> 2)) * K + k] : 0.0f;
    __half h = __float2half_rn(v);
    bh[id] = h;
    bl[id] = __float2half_rn((v - __half2float(h)) * 2048.0f);
}

// ===========================================================================
// gemm_half: xg[M,Ntot] = A planes @ Wperm planes^T + biasperm  (unchanged R6)
// ===========================================================================
#define GS 3
#define G_STG 20480
#define GEMM_SMEM (GS * G_STG * 2 + 512)

__device__ __forceinline__ void g_load(uint32_t smb, int stage,
    const __half* __restrict__ Ah, const __half* __restrict__ Al,
    const __half* __restrict__ Bh, const __half* __restrict__ Bl,
    int m0, int n0, int KP, int k0, int tid)
{
#pragma unroll
    for (int it = 0; it < 4; ++it) {
        int g = tid + it * 256;
        int pl = g >> 9, r = (g >> 2) & 127, cg = g & 3;
        const __half* src = (pl ? Al : Ah) + (size_t)(m0 + r) * KP + k0 + cg * 8;
        cp16(smb + 2 * (stage * G_STG + pl * 5120 + r * 40 + cg * 8), src);
    }
#pragma unroll
    for (int it = 0; it < 4; ++it) {
        int g = tid + it * 256;
        int pl = g >> 9, r = (g >> 2) & 127, cg = g & 3;
        const __half* src = (pl ? Bl : Bh) + (size_t)(n0 + r) * KP + k0 + cg * 8;
        cp16(smb + 2 * (stage * G_STG + 10240 + pl * 5120 + r * 40 + cg * 8), src);
    }
}

extern __shared__ __half hsm[];

__global__ __launch_bounds__(256) void gemm_half(
    const __half* __restrict__ Ah, const __half* __restrict__ Al,
    const __half* __restrict__ Bh, const __half* __restrict__ Bl,
    const float* __restrict__ bias, float* __restrict__ C,
    int Ntot, int KP, int H)
{
    const int tid = threadIdx.x;
    const int lane = tid & 31, wid = tid >> 5;
    const int qt = lane & 3, qd = lane >> 2;
    const int n0 = blockIdx.x * 128;
    const int m0 = blockIdx.y * 128;
    const int wm = (wid >> 1) * 32, wn = (wid & 1) * 64;
    const uint32_t smb = smem_u32(hsm);

    float* bs = (float*)(hsm + GS * G_STG);
    if (tid < 128) {
        int n = n0 + tid;
        bs[tid] = (n < Ntot) ? bias[(size_t)(n & 3) * H + (n >> 2)] : 0.0f;
    }

    float acc0[2][8][4] = {}, acc1[2][8][4] = {};
    const int nt = KP / 32;

#pragma unroll
    for (int s = 0; s < GS - 1; ++s) {
        g_load(smb, s, Ah, Al, Bh, Bl, m0, n0, KP, s * 32, tid);
        cp_commit();
    }

    for (int i = 0; i < nt; ++i) {
        if (i + GS - 1 < nt)
            g_load(smb, (i + GS - 1) % GS, Ah, Al, Bh, Bl, m0, n0, KP, (i + GS - 1) * 32, tid);
        cp_commit();
        cp_wait<GS - 1>();
        __syncthreads();

        const uint32_t sb = smb + 2 * ((i % GS) * G_STG);
#pragma unroll
        for (int s = 0; s < 2; ++s) {
            const int k0 = s * 16;
            uint32_t afh[2][4], afl[2][4];
#pragma unroll
            for (int mt = 0; mt < 2; ++mt) {
                uint32_t arow = wm + mt * 16 + (lane & 15);
                uint32_t acol = k0 + (lane >> 4) * 8;
                ldsm4(afh[mt], sb + 2 * (arow * 40 + acol));
                ldsm4(afl[mt], sb + 2 * (5120u + arow * 40 + acol));
            }
#pragma unroll
            for (int gp = 0; gp < 4; ++gp) {
                uint32_t brow = wn + gp * 16 + ((lane >> 4) & 1) * 8 + (lane & 7);
                uint32_t bcol = k0 + ((lane >> 3) & 1) * 8;
                uint32_t tb[4], tl[4];
                ldsm4(tb, sb + 2 * (10240u + brow * 40 + bcol));
                ldsm4(tl, sb + 2 * (15360u + brow * 40 + bcol));
#pragma unroll
                for (int mt = 0; mt < 2; ++mt)
#pragma unroll
                    for (int j = 0; j < 2; ++j) {
                        int ntl = gp * 2 + j;
                        mma_h(acc0[mt][ntl], afh[mt], tb[j * 2], tb[j * 2 + 1]);
                        mma_h(acc1[mt][ntl], afh[mt], tl[j * 2], tl[j * 2 + 1]);
                        mma_h(acc1[mt][ntl], afl[mt], tb[j * 2], tb[j * 2 + 1]);
                    }
            }
        }
        __syncthreads();
    }

#pragma unroll
    for (int mt = 0; mt < 2; ++mt) {
        int row = m0 + wm + mt * 16 + qd;
#pragma unroll
        for (int ntl = 0; ntl < 8; ++ntl) {
            int cl = wn + ntl * 8 + 2 * qt;
            int col = n0 + cl;
            if (col < Ntot) {
                float b0 = bs[cl], b1 = bs[cl + 1];
                float2 v0, v1;
                v0.x = acc0[mt][ntl][0] + acc1[mt][ntl][0] * INV2048 + b0;
                v0.y = acc0[mt][ntl][1] + acc1[mt][ntl][1] * INV2048 + b1;
                v1.x = acc0[mt][ntl][2] + acc1[mt][ntl][2] * INV2048 + b0;
                v1.y = acc0[mt][ntl][3] + acc1[mt][ntl][3] * INV2048 + b1;
                *(float2*)(C + (size_t)row * Ntot + col) = v0;
                *(float2*)(C + (size_t)(row + 8) * Ntot + col) = v1;
            }
        }
    }
}

// ===========================================================================
// lstm_persist: ALL timesteps of one layer in a single launch.
// CTA = 32 gate-cols (8 hidden units) x 128 batch; weights resident in SMEM;
// cell state in registers; software grid barrier between steps.
// SMEM (halves): WH[32][WSTR] | WL[32][WSTR] | stages[3][AH 5120 | AL 5120]
// ===========================================================================
#define LS 3

__global__ __launch_bounds__(256) void lstm_persist(
    const float* __restrict__ xg,     // [T][B][Ntot]
    __half* __restrict__ ah,          // [T+1][B][KP]
    __half* __restrict__ al,
    const __half* __restrict__ wH, const __half* __restrict__ wL,
    float* __restrict__ out,          // [T][B][H]
    unsigned* __restrict__ ctr,
    int H, int KP)
{
    const int Ntot = 4 * H;
    const int WSTR = KP + 8;
    const int tid = threadIdx.x;
    const int lane = tid & 31, wid = tid >> 5;
    const int qt = lane & 3, qd = lane >> 2;
    const int n0 = blockIdx.x * 32;
    const int wm = (wid >> 1) * 32, wn = (wid & 1) * 16;
    const uint32_t smb = smem_u32(hsm);
    const uint32_t SOFF = 64u * (uint32_t)WSTR;   // stage base (halves)
    const int nt = KP / 32;
    const unsigned nCTA = gridDim.x;

    // ---- preload weight tile (rows n0..n0+31, hi+lo) into SMEM ----
    {
        const int kops = KP / 8;
        for (int i = tid; i < 32 * kops; i += 256) {
            int r = i / kops, c = (i - r * kops) * 8;
            cp16(smb + 2 * (uint32_t)(r * WSTR + c), wH + (size_t)(n0 + r) * KP + c);
            cp16(smb + 2 * (uint32_t)((32 + r) * WSTR + c), wL + (size_t)(n0 + r) * KP + c);
        }
        cp_commit();
        cp_wait<0>();
        __syncthreads();
    }

    float c4[4] = {0.f, 0.f, 0.f, 0.f};
    const int b = wm + lane;
    const int nbase = n0 + wn;

#define PL_LOAD(STAGE, K0)                                                    \
    {                                                                         \
        _Pragma("unroll")                                                     \
        for (int it = 0; it < 4; ++it) {                                      \
            int g = tid + it * 256;                                           \
            int pl = g >> 9, r = (g >> 2) & 127, cg = g & 3;                  \
            const __half* src = (pl ? hL : hH) + (size_t)r * KP + (K0) + cg * 8; \
            cp16(smb + 2 * (SOFF + (STAGE) * 10240u + pl * 5120u + r * 40u + cg * 8u), src); \
        }                                                                     \
    }

    for (int t = 0; t < T_SEQ; ++t) {
        const __half* hH = ah + (size_t)t * BATCH * KP;
        const __half* hL = al + (size_t)t * BATCH * KP;

        float acc0[2][2][4] = {}, acc1[2][2][4] = {};

#pragma unroll
        for (int s = 0; s < LS - 1; ++s) {
            PL_LOAD(s, s * 32);
            cp_commit();
        }

        for (int i = 0; i < nt; ++i) {
            if (i + LS - 1 < nt) PL_LOAD((i + LS - 1) % LS, (i + LS - 1) * 32);
            cp_commit();
            cp_wait<LS - 1>();
            __syncthreads();

            const uint32_t sa = smb + 2 * (SOFF + (uint32_t)(i % LS) * 10240u);
            const int kb = i * 32;
#pragma unroll
            for (int s = 0; s < 2; ++s) {
                const int k0 = s * 16;
                uint32_t afh[2][4], afl[2][4];
#pragma unroll
                for (int mt = 0; mt < 2; ++mt) {
                    uint32_t arow = wm + mt * 16 + (lane & 15);
                    uint32_t acol = k0 + (lane >> 4) * 8;
                    ldsm4(afh[mt], sa + 2 * (arow * 40 + acol));
                    ldsm4(afl[mt], sa + 2 * (5120u + arow * 40 + acol));
                }
                uint32_t bh[2][2], bl[2][2];
                {
                    uint32_t brow = wn + ((lane >> 4) & 1) * 8 + (lane & 7);
                    uint32_t bcol = (uint32_t)(kb + k0) + ((lane >> 3) & 1) * 8;
                    uint32_t t4[4];
                    ldsm4(t4, smb + 2 * (brow * (uint32_t)WSTR + bcol));
                    bh[0][0] = t4[0]; bh[0][1] = t4[1]; bh[1][0] = t4[2]; bh[1][1] = t4[3];
                    ldsm4(t4, smb + 2 * ((brow + 32u) * (uint32_t)WSTR + bcol));
                    bl[0][0] = t4[0]; bl[0][1] = t4[1]; bl[1][0] = t4[2]; bl[1][1] = t4[3];
                }
#pragma unroll
                for (int mt = 0; mt < 2; ++mt)
#pragma unroll
                    for (int ntl = 0; ntl < 2; ++ntl) {
                        mma_h(acc0[mt][ntl], afh[mt], bh[ntl][0], bh[ntl][1]);
                        mma_h(acc1[mt][ntl], afh[mt], bl[ntl][0], bl[ntl][1]);
                        mma_h(acc1[mt][ntl], afl[mt], bh[ntl][0], bh[ntl][1]);
                    }
            }
            __syncthreads();
        }

        // ---- gate epilogue (overlay on stage region; stages idle) ----
        float* gsm = (float*)(hsm + SOFF) + wid * (32 * 20);
#pragma unroll
        for (int mt = 0; mt < 2; ++mt)
#pragma unroll
            for (int ntl = 0; ntl < 2; ++ntl) {
                int r0 = mt * 16 + qd;
                int c0 = ntl * 8 + 2 * qt;
                gsm[r0 * 20 + c0]           = acc0[mt][ntl][0] + acc1[mt][ntl][0] * INV2048;
                gsm[r0 * 20 + c0 + 1]       = acc0[mt][ntl][1] + acc1[mt][ntl][1] * INV2048;
                gsm[(r0 + 8) * 20 + c0]     = acc0[mt][ntl][2] + acc1[mt][ntl][2] * INV2048;
                gsm[(r0 + 8) * 20 + c0 + 1] = acc0[mt][ntl][3] + acc1[mt][ntl][3] * INV2048;
            }
        __syncwarp();

        __half* nH = ah + (size_t)(t + 1) * BATCH * KP;
        __half* nL = al + (size_t)(t + 1) * BATCH * KP;
        const float* xgb = xg + ((size_t)t * BATCH + b) * Ntot;
        float* ob = out + ((size_t)t * BATCH + b) * H;
#pragma unroll
        for (int u = 0; u < 4; ++u) {
            int colg = nbase + 4 * u;
            if (colg < Ntot) {
                int j = colg >> 2;
                float4 g4 = *(float4*)&gsm[lane * 20 + 4 * u];
                float4 x4 = *(const float4*)(xgb + colg);
                float pi = g4.x + x4.x;
                float pf = g4.y + x4.y;
                float pg = g4.z + x4.z;
                float po = g4.w + x4.w;
                float cc = sigm(pf) * c4[u] + sigm(pi) * tanhf(pg);
                c4[u] = cc;
                float h = sigm(po) * tanhf(cc);
                ob[j] = h;
                __half hh = __float2half_rn(h);
                size_t pidx = (size_t)b * KP + j;
                nH[pidx] = hh;
                nL[pidx] = __float2half_rn((h - __half2float(hh)) * 2048.0f);
            }
        }

        // ---- grid barrier ----
        __threadfence();
        __syncthreads();
        if (tid == 0) {
            atomicAdd(ctr, 1u);
            unsigned tgt = nCTA * (unsigned)(t + 1);
            unsigned v;
            do {
                asm volatile("ld.global.acquire.gpu.u32 %0, [%1];" : "=r"(v) : "l"(ctr));
                if (v >= tgt) break;
                __nanosleep(64);
            } while (true);
        }
        __syncthreads();
    }
#undef PL_LOAD
}

// ---------------------------------------------------------------------------
extern "C" void kernel_launch(void* const* d_in, const int* in_sizes, int n_in,
                              void* d_out, int out_size) {
    const int*   tokens = (const int*)d_in[0];
    const float* emb    = (const float*)d_in[1];
    const float* Wih[3] = {(const float*)d_in[2], (const float*)d_in[5], (const float*)d_in[8]};
    const float* Whh[3] = {(const float*)d_in[3], (const float*)d_in[6], (const float*)d_in[9]};
    const float* bb[3]  = {(const float*)d_in[4], (const float*)d_in[7], (const float*)d_in[10]};
    float* out = (float*)d_out;

    float *xg;
    __half *ah, *al, *wbh, *wbl;
    unsigned* ctr;
    cudaGetSymbolAddress((void**)&xg,  g_xg);
    cudaGetSymbolAddress((void**)&ah,  g_ah);
    cudaGetSymbolAddress((void**)&al,  g_al);
    cudaGetSymbolAddress((void**)&wbh, g_wbh);
    cudaGetSymbolAddress((void**)&wbl, g_wbl);
    cudaGetSymbolAddress((void**)&ctr, g_ctr);

    const int PSMEM_MAX = (64 * (1152 + 8) + LS * 10240) * 2;  // 209920
    cudaFuncSetAttribute(gemm_half,    cudaFuncAttributeMaxDynamicSharedMemorySize, GEMM_SMEM);
    cudaFuncSetAttribute(lstm_persist, cudaFuncAttributeMaxDynamicSharedMemorySize, PSMEM_MAX);

    cudaMemsetAsync(ctr, 0, 4 * sizeof(unsigned));
    embed_split<<<MROWS, 128>>>(tokens, emb, ah, al);

    const int Hs[3]   = {1150, 1150, 400};
    const int Kin[3]  = {400, 1150, 1150};
    const int KPin[3] = {416, 1152, 1152};
    const int HPs[3]  = {1152, 1152, 416};
    const size_t outoff[3] = {0, (size_t)MROWS * 1150, (size_t)MROWS * 1150 * 2};

    for (int l = 0; l < 3; ++l) {
        const int H = Hs[l], K = Kin[l], KP = KPin[l], HP = HPs[l], N = 4 * H;

        // input-weight planes + GEMM for xg
        split_w<<<(4 * H * KP + 255) / 256, 256>>>(Wih[l], wbh, wbl, H, K, KP);
        const __half* Asrc_h = (l == 0) ? ah : (ah + (size_t)BATCH * 1152);
        const __half* Asrc_l = (l == 0) ? al : (al + (size_t)BATCH * 1152);
        dim3 gg((N + 127) / 128, MROWS / 128);
        gemm_half<<<gg, 256, GEMM_SMEM>>>(Asrc_h, Asrc_l, wbh, wbl, bb[l], xg, N, KP, H);

        // reset h-plane buffer (zeroes slot 0 and pad cols)
        cudaMemsetAsync(ah, 0, (size_t)(T_SEQ + 1) * BATCH * HP * 2);
        cudaMemsetAsync(al, 0, (size_t)(T_SEQ + 1) * BATCH * HP * 2);

        // recurrent-weight planes
        split_w<<<(4 * H * HP + 255) / 256, 256>>>(Whh[l], wbh, wbl, H, H, HP);

        // persistent recurrent kernel: all 200 steps in one launch
        const int nblk = (N + 31) / 32;   // 144 or 50  (<= 148 SMs, wave-1 resident)
        const int psm = (64 * (HP + 8) + LS * 10240) * 2;
        lstm_persist<<<nblk, 256, psm>>>(xg, ah, al, wbh, wbl,
                                         out + outoff[l], ctr + l, H, HP);
    }
}

// round 8
// speedup vs baseline: 2.8022x; 1.0572x over previous
#include <cuda_runtime.h>
#include <cuda_fp16.h>
#include <math.h>
#include <stdint.h>

#define T_SEQ 200
#define BATCH 128
#define MROWS (T_SEQ * BATCH)   // 25600
#define INV2048 (1.0f / 2048.0f)

// ---- device-global scratch ----
__device__ float  g_xg[(size_t)MROWS * 4600];
__device__ __half g_ah[(size_t)(T_SEQ + 1) * BATCH * 1152];  // A planes / h planes
__device__ __half g_al[(size_t)(T_SEQ + 1) * BATCH * 1152];
__device__ __half g_wbh[(size_t)4608 * 1152];                // weight planes
__device__ __half g_wbl[(size_t)4608 * 1152];
__device__ unsigned g_flags[512];                            // [0..255] CTA flags, [256] go-word

// ===========================================================================
// PTX helpers (sm_80-era, safe on plain sm_103 target)
// ===========================================================================
__device__ __forceinline__ uint32_t smem_u32(const void* p) {
    uint32_t a;
    asm("{ .reg .u64 t; cvta.to.shared.u64 t, %1; cvt.u32.u64 %0, t; }" : "=r"(a) : "l"(p));
    return a;
}
__device__ __forceinline__ void cp16(uint32_t s, const void* g) {
    asm volatile("cp.async.cg.shared.global [%0], [%1], 16;" :: "r"(s), "l"(g));
}
__device__ __forceinline__ void cp_commit() {
    asm volatile("cp.async.commit_group;");
}
template <int N> __device__ __forceinline__ void cp_wait() {
    asm volatile("cp.async.wait_group %0;" :: "n"(N));
}
__device__ __forceinline__ void ldsm4(uint32_t* r, uint32_t a) {
    asm volatile("ldmatrix.sync.aligned.m8n8.x4.shared.b16 {%0,%1,%2,%3}, [%4];"
        : "=r"(r[0]), "=r"(r[1]), "=r"(r[2]), "=r"(r[3]) : "r"(a));
}
__device__ __forceinline__ void mma_h(float* d, const uint32_t* a, uint32_t b0, uint32_t b1) {
    asm volatile("mma.sync.aligned.m16n8k16.row.col.f32.f16.f16.f32 "
        "{%0,%1,%2,%3}, {%4,%5,%6,%7}, {%8,%9}, {%0,%1,%2,%3};"
        : "+f"(d[0]), "+f"(d[1]), "+f"(d[2]), "+f"(d[3])
        : "r"(a[0]), "r"(a[1]), "r"(a[2]), "r"(a[3]), "r"(b0), "r"(b1));
}
__device__ __forceinline__ void st_rel(unsigned* p, unsigned v) {
    asm volatile("st.global.release.gpu.u32 [%0], %1;" :: "l"(p), "r"(v) : "memory");
}
__device__ __forceinline__ unsigned ld_acq(const unsigned* p) {
    unsigned v;
    asm volatile("ld.global.acquire.gpu.u32 %0, [%1];" : "=r"(v) : "l"(p) : "memory");
    return v;
}
__device__ __forceinline__ float sigm(float x) { return 1.0f / (1.0f + expf(-x)); }

// ===========================================================================
// Pre-split kernels
// ===========================================================================
__global__ void embed_split(const int* __restrict__ tokens,
                            const float* __restrict__ emb,
                            __half* __restrict__ ah, __half* __restrict__ al) {
    int row = blockIdx.x;
    int tok = tokens[row];
    const float* src = emb + (size_t)tok * 400;
    __half* dh = ah + (size_t)row * 416;
    __half* dl = al + (size_t)row * 416;
    for (int i = threadIdx.x; i < 416; i += blockDim.x) {
        float v = (i < 400) ? src[i] : 0.0f;
        __half h = __float2half_rn(v);
        dh[i] = h;
        dl[i] = __float2half_rn((v - __half2float(h)) * 2048.0f);
    }
}

// split + gate-permute weights: out row n = (4j+g) <- src row (g*H+j); zero-pad k>=K
__global__ void split_w(const float* __restrict__ W,
                        __half* __restrict__ bh, __half* __restrict__ bl,
                        int H, int K, int KP) {
    int id = blockIdx.x * 256 + threadIdx.x;
    int total = 4 * H * KP;
    if (id >= total) return;
    int n = id / KP, k = id - n * KP;
    float v = (k < K) ? W[(size_t)((n & 3) * H + (n >> 2)) * K + k] : 0.0f;
    __half h = __float2half_rn(v);
    bh[id] = h;
    bl[id] = __float2half_rn((v - __half2float(h)) * 2048.0f);
}

// ===========================================================================
// gemm_half: xg[M,Ntot] = A planes @ Wperm planes^T + biasperm  (proven R6)
// ===========================================================================
#define GS 3
#define G_STG 20480
#define GEMM_SMEM (GS * G_STG * 2 + 512)

__device__ __forceinline__ void g_load(uint32_t smb, int stage,
    const __half* __restrict__ Ah, const __half* __restrict__ Al,
    const __half* __restrict__ Bh, const __half* __restrict__ Bl,
    int m0, int n0, int KP, int k0, int tid)
{
#pragma unroll
    for (int it = 0; it < 4; ++it) {
        int g = tid + it * 256;
        int pl = g >> 9, r = (g >> 2) & 127, cg = g & 3;
        const __half* src = (pl ? Al : Ah) + (size_t)(m0 + r) * KP + k0 + cg * 8;
        cp16(smb + 2 * (stage * G_STG + pl * 5120 + r * 40 + cg * 8), src);
    }
#pragma unroll
    for (int it = 0; it < 4; ++it) {
        int g = tid + it * 256;
        int pl = g >> 9, r = (g >> 2) & 127, cg = g & 3;
        const __half* src = (pl ? Bl : Bh) + (size_t)(n0 + r) * KP + k0 + cg * 8;
        cp16(smb + 2 * (stage * G_STG + 10240 + pl * 5120 + r * 40 + cg * 8), src);
    }
}

extern __shared__ __half hsm[];

__global__ __launch_bounds__(256) void gemm_half(
    const __half* __restrict__ Ah, const __half* __restrict__ Al,
    const __half* __restrict__ Bh, const __half* __restrict__ Bl,
    const float* __restrict__ bias, float* __restrict__ C,
    int Ntot, int KP, int H)
{
    const int tid = threadIdx.x;
    const int lane = tid & 31, wid = tid >> 5;
    const int qt = lane & 3, qd = lane >> 2;
    const int n0 = blockIdx.x * 128;
    const int m0 = blockIdx.y * 128;
    const int wm = (wid >> 1) * 32, wn = (wid & 1) * 64;
    const uint32_t smb = smem_u32(hsm);

    float* bs = (float*)(hsm + GS * G_STG);
    if (tid < 128) {
        int n = n0 + tid;
        bs[tid] = (n < Ntot) ? bias[(size_t)(n & 3) * H + (n >> 2)] : 0.0f;
    }

    float acc0[2][8][4] = {}, acc1[2][8][4] = {};
    const int nt = KP / 32;

#pragma unroll
    for (int s = 0; s < GS - 1; ++s) {
        g_load(smb, s, Ah, Al, Bh, Bl, m0, n0, KP, s * 32, tid);
        cp_commit();
    }

    for (int i = 0; i < nt; ++i) {
        if (i + GS - 1 < nt)
            g_load(smb, (i + GS - 1) % GS, Ah, Al, Bh, Bl, m0, n0, KP, (i + GS - 1) * 32, tid);
        cp_commit();
        cp_wait<GS - 1>();
        __syncthreads();

        const uint32_t sb = smb + 2 * ((i % GS) * G_STG);
#pragma unroll
        for (int s = 0; s < 2; ++s) {
            const int k0 = s * 16;
            uint32_t afh[2][4], afl[2][4];
#pragma unroll
            for (int mt = 0; mt < 2; ++mt) {
                uint32_t arow = wm + mt * 16 + (lane & 15);
                uint32_t acol = k0 + (lane >> 4) * 8;
                ldsm4(afh[mt], sb + 2 * (arow * 40 + acol));
                ldsm4(afl[mt], sb + 2 * (5120u + arow * 40 + acol));
            }
#pragma unroll
            for (int gp = 0; gp < 4; ++gp) {
                uint32_t brow = wn + gp * 16 + ((lane >> 4) & 1) * 8 + (lane & 7);
                uint32_t bcol = k0 + ((lane >> 3) & 1) * 8;
                uint32_t tb[4], tl[4];
                ldsm4(tb, sb + 2 * (10240u + brow * 40 + bcol));
                ldsm4(tl, sb + 2 * (15360u + brow * 40 + bcol));
#pragma unroll
                for (int mt = 0; mt < 2; ++mt)
#pragma unroll
                    for (int j = 0; j < 2; ++j) {
                        int ntl = gp * 2 + j;
                        mma_h(acc0[mt][ntl], afh[mt], tb[j * 2], tb[j * 2 + 1]);
                        mma_h(acc1[mt][ntl], afh[mt], tl[j * 2], tl[j * 2 + 1]);
                        mma_h(acc1[mt][ntl], afl[mt], tb[j * 2], tb[j * 2 + 1]);
                    }
            }
        }
        __syncthreads();
    }

#pragma unroll
    for (int mt = 0; mt < 2; ++mt) {
        int row = m0 + wm + mt * 16 + qd;
#pragma unroll
        for (int ntl = 0; ntl < 8; ++ntl) {
            int cl = wn + ntl * 8 + 2 * qt;
            int col = n0 + cl;
            if (col < Ntot) {
                float b0 = bs[cl], b1 = bs[cl + 1];
                float2 v0, v1;
                v0.x = acc0[mt][ntl][0] + acc1[mt][ntl][0] * INV2048 + b0;
                v0.y = acc0[mt][ntl][1] + acc1[mt][ntl][1] * INV2048 + b1;
                v1.x = acc0[mt][ntl][2] + acc1[mt][ntl][2] * INV2048 + b0;
                v1.y = acc0[mt][ntl][3] + acc1[mt][ntl][3] * INV2048 + b1;
                *(float2*)(C + (size_t)row * Ntot + col) = v0;
                *(float2*)(C + (size_t)(row + 8) * Ntot + col) = v1;
            }
        }
    }
}

// ===========================================================================
// lstm_persist: ALL timesteps of one layer in one launch.
// Weights SMEM-resident; K-chunk 64, 2 stages; flag-array grid barrier.
// SMEM (halves): WH[32][WSTR] | WL[32][WSTR] | stages[2][AH 9216 | AL 9216]
// ===========================================================================
#define LKC 64
#define LSTG 18432u   // halves per stage (2 planes x 128 x 72)

__global__ __launch_bounds__(256) void lstm_persist(
    const float* __restrict__ xg,     // [T][B][Ntot]
    __half* __restrict__ ah,          // [T+1][B][KP]
    __half* __restrict__ al,
    const __half* __restrict__ wH, const __half* __restrict__ wL,
    float* __restrict__ out,          // [T][B][H]
    unsigned* __restrict__ flags,     // [256] per-CTA flags; flags[256] = go word
    int H, int KP)
{
    const int Ntot = 4 * H;
    const int WSTR = KP + 8;
    const int tid = threadIdx.x;
    const int lane = tid & 31, wid = tid >> 5;
    const int qt = lane & 3, qd = lane >> 2;
    const int n0 = blockIdx.x * 32;
    const int wm = (wid >> 1) * 32, wn = (wid & 1) * 16;
    const uint32_t smb = smem_u32(hsm);
    const uint32_t SOFF = 64u * (uint32_t)WSTR;   // stage base (halves)
    const int nt = KP / LKC;
    const unsigned nCTA = gridDim.x;
    unsigned* gow = flags + 256;

    // ---- preload weight tile (rows n0..n0+31, hi+lo) into SMEM ----
    {
        const int kops = KP / 8;
        for (int i = tid; i < 32 * kops; i += 256) {
            int r = i / kops, c = (i - r * kops) * 8;
            cp16(smb + 2 * (uint32_t)(r * WSTR + c), wH + (size_t)(n0 + r) * KP + c);
            cp16(smb + 2 * (uint32_t)((32 + r) * WSTR + c), wL + (size_t)(n0 + r) * KP + c);
        }
        cp_commit();
        cp_wait<0>();
        __syncthreads();
    }

    float c4[4] = {0.f, 0.f, 0.f, 0.f};
    const int b = wm + lane;
    const int nbase = n0 + wn;

#define PL_LOAD(STAGE, K0)                                                    \
    {                                                                         \
        _Pragma("unroll")                                                     \
        for (int it = 0; it < 8; ++it) {                                      \
            int g = tid + it * 256;                                           \
            int pl = g >> 10, r = (g >> 3) & 127, cg = g & 7;                 \
            const __half* src = (pl ? hL : hH) + (size_t)r * KP + (K0) + cg * 8; \
            cp16(smb + 2 * (SOFF + (STAGE) * LSTG + pl * 9216u + r * 72u + cg * 8u), src); \
        }                                                                     \
    }

    for (int t = 0; t < T_SEQ; ++t) {
        const __half* hH = ah + (size_t)t * BATCH * KP;
        const __half* hL = al + (size_t)t * BATCH * KP;

        float acc0[2][2][4] = {}, acc1[2][2][4] = {};

        PL_LOAD(0, 0);
        cp_commit();

        for (int i = 0; i < nt; ++i) {
            if (i + 1 < nt) PL_LOAD((i + 1) & 1, (i + 1) * LKC);
            cp_commit();
            cp_wait<1>();
            __syncthreads();

            const uint32_t sa = smb + 2 * (SOFF + (uint32_t)(i & 1) * LSTG);
            const int kb = i * LKC;
#pragma unroll
            for (int s = 0; s < 4; ++s) {
                const int k0 = s * 16;
                uint32_t afh[2][4], afl[2][4];
#pragma unroll
                for (int mt = 0; mt < 2; ++mt) {
                    uint32_t arow = wm + mt * 16 + (lane & 15);
                    uint32_t acol = k0 + (lane >> 4) * 8;
                    ldsm4(afh[mt], sa + 2 * (arow * 72 + acol));
                    ldsm4(afl[mt], sa + 2 * (9216u + arow * 72 + acol));
                }
                uint32_t bh[2][2], bl[2][2];
                {
                    uint32_t brow = wn + ((lane >> 4) & 1) * 8 + (lane & 7);
                    uint32_t bcol = (uint32_t)(kb + k0) + ((lane >> 3) & 1) * 8;
                    uint32_t t4[4];
                    ldsm4(t4, smb + 2 * (brow * (uint32_t)WSTR + bcol));
                    bh[0][0] = t4[0]; bh[0][1] = t4[1]; bh[1][0] = t4[2]; bh[1][1] = t4[3];
                    ldsm4(t4, smb + 2 * ((brow + 32u) * (uint32_t)WSTR + bcol));
                    bl[0][0] = t4[0]; bl[0][1] = t4[1]; bl[1][0] = t4[2]; bl[1][1] = t4[3];
                }
#pragma unroll
                for (int mt = 0; mt < 2; ++mt)
#pragma unroll
                    for (int ntl = 0; ntl < 2; ++ntl) {
                        mma_h(acc0[mt][ntl], afh[mt], bh[ntl][0], bh[ntl][1]);
                        mma_h(acc1[mt][ntl], afh[mt], bl[ntl][0], bl[ntl][1]);
                        mma_h(acc1[mt][ntl], afl[mt], bh[ntl][0], bh[ntl][1]);
                    }
            }
            __syncthreads();
        }

        // ---- gate epilogue (overlay on stage region; stages idle) ----
        float* gsm = (float*)(hsm + SOFF) + wid * (32 * 20);
#pragma unroll
        for (int mt = 0; mt < 2; ++mt)
#pragma unroll
            for (int ntl = 0; ntl < 2; ++ntl) {
                int r0 = mt * 16 + qd;
                int c0 = ntl * 8 + 2 * qt;
                gsm[r0 * 20 + c0]           = acc0[mt][ntl][0] + acc1[mt][ntl][0] * INV2048;
                gsm[r0 * 20 + c0 + 1]       = acc0[mt][ntl][1] + acc1[mt][ntl][1] * INV2048;
                gsm[(r0 + 8) * 20 + c0]     = acc0[mt][ntl][2] + acc1[mt][ntl][2] * INV2048;
                gsm[(r0 + 8) * 20 + c0 + 1] = acc0[mt][ntl][3] + acc1[mt][ntl][3] * INV2048;
            }
        __syncwarp();

        __half* nH = ah + (size_t)(t + 1) * BATCH * KP;
        __half* nL = al + (size_t)(t + 1) * BATCH * KP;
        const float* xgb = xg + ((size_t)t * BATCH + b) * Ntot;
        float* ob = out + ((size_t)t * BATCH + b) * H;
#pragma unroll
        for (int u = 0; u < 4; ++u) {
            int colg = nbase + 4 * u;
            if (colg < Ntot) {
                int j = colg >> 2;
                float4 g4 = *(float4*)&gsm[lane * 20 + 4 * u];
                float4 x4 = *(const float4*)(xgb + colg);
                float pi = g4.x + x4.x;
                float pf = g4.y + x4.y;
                float pg = g4.z + x4.z;
                float po = g4.w + x4.w;
                float cc = sigm(pf) * c4[u] + sigm(pi) * tanhf(pg);
                c4[u] = cc;
                float h = sigm(po) * tanhf(cc);
                ob[j] = h;
                __half hh = __float2half_rn(h);
                size_t pidx = (size_t)b * KP + j;
                nH[pidx] = hh;
                nL[pidx] = __float2half_rn((h - __half2float(hh)) * 2048.0f);
            }
        }

        // ---- flag-array grid barrier ----
        __threadfence();
        __syncthreads();
        const unsigned epoch = (unsigned)(t + 1);
        if (tid == 0) st_rel(flags + blockIdx.x, epoch);
        if (blockIdx.x == 0) {
            if (tid < nCTA) {
                while (ld_acq(flags + tid) < epoch) __nanosleep(32);
            }
            __syncthreads();
            if (tid == 0) st_rel(gow, epoch);
        } else {
            if (tid == 0) {
                while (ld_acq(gow) < epoch) __nanosleep(32);
            }
            __syncthreads();
        }
    }
#undef PL_LOAD
}

// ---------------------------------------------------------------------------
extern "C" void kernel_launch(void* const* d_in, const int* in_sizes, int n_in,
                              void* d_out, int out_size) {
    const int*   tokens = (const int*)d_in[0];
    const float* emb    = (const float*)d_in[1];
    const float* Wih[3] = {(const float*)d_in[2], (const float*)d_in[5], (const float*)d_in[8]};
    const float* Whh[3] = {(const float*)d_in[3], (const float*)d_in[6], (const float*)d_in[9]};
    const float* bb[3]  = {(const float*)d_in[4], (const float*)d_in[7], (const float*)d_in[10]};
    float* out = (float*)d_out;

    float *xg;
    __half *ah, *al, *wbh, *wbl;
    unsigned* flags;
    cudaGetSymbolAddress((void**)&xg,  g_xg);
    cudaGetSymbolAddress((void**)&ah,  g_ah);
    cudaGetSymbolAddress((void**)&al,  g_al);
    cudaGetSymbolAddress((void**)&wbh, g_wbh);
    cudaGetSymbolAddress((void**)&wbl, g_wbl);
    cudaGetSymbolAddress((void**)&flags, g_flags);

    const int PSMEM_MAX = (64 * (1152 + 8) + 2 * (int)LSTG) * 2;  // 222208
    cudaFuncSetAttribute(gemm_half,    cudaFuncAttributeMaxDynamicSharedMemorySize, GEMM_SMEM);
    cudaFuncSetAttribute(lstm_persist, cudaFuncAttributeMaxDynamicSharedMemorySize, PSMEM_MAX);

    embed_split<<<MROWS, 128>>>(tokens, emb, ah, al);

    const int Hs[3]   = {1150, 1150, 400};
    const int Kin[3]  = {400, 1150, 1150};
    const int KPin[3] = {416, 1152, 1152};
    const int HPs[3]  = {1152, 1152, 448};   // recurrent K padded to x64
    const size_t outoff[3] = {0, (size_t)MROWS * 1150, (size_t)MROWS * 1150 * 2};

    for (int l = 0; l < 3; ++l) {
        const int H = Hs[l], K = Kin[l], KP = KPin[l], HP = HPs[l], N = 4 * H;

        // input-weight planes + GEMM for xg
        split_w<<<(4 * H * KP + 255) / 256, 256>>>(Wih[l], wbh, wbl, H, K, KP);
        const __half* Asrc_h = (l == 0) ? ah : (ah + (size_t)BATCH * 1152);
        const __half* Asrc_l = (l == 0) ? al : (al + (size_t)BATCH * 1152);
        dim3 gg((N + 127) / 128, MROWS / 128);
        gemm_half<<<gg, 256, GEMM_SMEM>>>(Asrc_h, Asrc_l, wbh, wbl, bb[l], xg, N, KP, H);

        // reset h-plane buffer (zeroes slot 0 and pad cols) + barrier flags
        cudaMemsetAsync(ah, 0, (size_t)(T_SEQ + 1) * BATCH * HP * 2);
        cudaMemsetAsync(al, 0, (size_t)(T_SEQ + 1) * BATCH * HP * 2);
        cudaMemsetAsync(flags, 0, 512 * sizeof(unsigned));

        // recurrent-weight planes
        split_w<<<(4 * H * HP + 255) / 256, 256>>>(Whh[l], wbh, wbl, H, H, HP);

        // persistent recurrent kernel: all 200 steps in one launch
        const int nblk = (N + 31) / 32;   // 144 or 50
        const int psm = (64 * (HP + 8) + 2 * (int)LSTG) * 2;
        lstm_persist<<<nblk, 256, psm>>>(xg, ah, al, wbh, wbl,
                                         out + outoff[l], flags, H, HP);
    }
}

// round 9
// speedup vs baseline: 3.8417x; 1.3709x over previous
#include <cuda_runtime.h>
#include <cuda_fp16.h>
#include <math.h>
#include <stdint.h>

#define T_SEQ 200
#define BATCH 128
#define MROWS (T_SEQ * BATCH)   // 25600
#define INV2048 (1.0f / 2048.0f)

// ---- device-global scratch ----
__device__ float  g_xg[(size_t)MROWS * 4600];
__device__ __half g_ah[(size_t)(T_SEQ + 1) * BATCH * 1152];  // A / h planes (hi)
__device__ __half g_al[(size_t)MROWS * 416];                 // embedding lo plane only
__device__ __half g_wbh[(size_t)4608 * 1152];                // weight planes
__device__ __half g_wbl[(size_t)4608 * 1152];
__device__ unsigned g_flags[512];                            // CTA flags + go-word

// ===========================================================================
// PTX helpers (sm_80-era, safe on plain sm_103 target)
// ===========================================================================
__device__ __forceinline__ uint32_t smem_u32(const void* p) {
    uint32_t a;
    asm("{ .reg .u64 t; cvta.to.shared.u64 t, %1; cvt.u32.u64 %0, t; }" : "=r"(a) : "l"(p));
    return a;
}
__device__ __forceinline__ void cp16(uint32_t s, const void* g) {
    asm volatile("cp.async.cg.shared.global [%0], [%1], 16;" :: "r"(s), "l"(g));
}
__device__ __forceinline__ void cp_commit() {
    asm volatile("cp.async.commit_group;");
}
template <int N> __device__ __forceinline__ void cp_wait() {
    asm volatile("cp.async.wait_group %0;" :: "n"(N));
}
__device__ __forceinline__ void ldsm4(uint32_t* r, uint32_t a) {
    asm volatile("ldmatrix.sync.aligned.m8n8.x4.shared.b16 {%0,%1,%2,%3}, [%4];"
        : "=r"(r[0]), "=r"(r[1]), "=r"(r[2]), "=r"(r[3]) : "r"(a));
}
__device__ __forceinline__ void mma_h(float* d, const uint32_t* a, uint32_t b0, uint32_t b1) {
    asm volatile("mma.sync.aligned.m16n8k16.row.col.f32.f16.f16.f32 "
        "{%0,%1,%2,%3}, {%4,%5,%6,%7}, {%8,%9}, {%0,%1,%2,%3};"
        : "+f"(d[0]), "+f"(d[1]), "+f"(d[2]), "+f"(d[3])
        : "r"(a[0]), "r"(a[1]), "r"(a[2]), "r"(a[3]), "r"(b0), "r"(b1));
}
__device__ __forceinline__ void st_rel(unsigned* p, unsigned v) {
    asm volatile("st.global.release.gpu.u32 [%0], %1;" :: "l"(p), "r"(v) : "memory");
}
__device__ __forceinline__ unsigned ld_acq(const unsigned* p) {
    unsigned v;
    asm volatile("ld.global.acquire.gpu.u32 %0, [%1];" : "=r"(v) : "l"(p) : "memory");
    return v;
}
__device__ __forceinline__ float sigm(float x) { return 1.0f / (1.0f + expf(-x)); }

// ===========================================================================
// Pre-split kernels
// ===========================================================================
__global__ void embed_split(const int* __restrict__ tokens,
                            const float* __restrict__ emb,
                            __half* __restrict__ ah, __half* __restrict__ al) {
    int row = blockIdx.x;
    int tok = tokens[row];
    const float* src = emb + (size_t)tok * 400;
    __half* dh = ah + (size_t)row * 416;
    __half* dl = al + (size_t)row * 416;
    for (int i = threadIdx.x; i < 416; i += blockDim.x) {
        float v = (i < 400) ? src[i] : 0.0f;
        __half h = __float2half_rn(v);
        dh[i] = h;
        dl[i] = __float2half_rn((v - __half2float(h)) * 2048.0f);
    }
}

// split + gate-permute weights: out row n = (4j+g) <- src row (g*H+j); zero-pad k>=K
__global__ void split_w(const float* __restrict__ W,
                        __half* __restrict__ bh, __half* __restrict__ bl,
                        int H, int K, int KP) {
    int id = blockIdx.x * 256 + threadIdx.x;
    int total = 4 * H * KP;
    if (id >= total) return;
    int n = id / KP, k = id - n * KP;
    float v = (k < K) ? W[(size_t)((n & 3) * H + (n >> 2)) * K + k] : 0.0f;
    __half h = __float2half_rn(v);
    bh[id] = h;
    bl[id] = __float2half_rn((v - __half2float(h)) * 2048.0f);
}

// ===========================================================================
// gemm_half<ALO>: xg = A @ Wperm^T + biasperm.  ALO: A has a lo plane (3 mma)
// else 2 mma. CTA 128x128, 8 warps, cp.async 3-stage.
// ===========================================================================
#define GS 3
#define G_STG 20480
#define GEMM_SMEM (GS * G_STG * 2 + 512)

extern __shared__ __half hsm[];

template <bool ALO>
__device__ __forceinline__ void g_load(uint32_t smb, int stage,
    const __half* __restrict__ Ah, const __half* __restrict__ Al,
    const __half* __restrict__ Bh, const __half* __restrict__ Bl,
    int m0, int n0, int KP, int k0, int tid)
{
#pragma unroll
    for (int it = 0; it < 4; ++it) {
        int g = tid + it * 256;
        int pl = g >> 9, r = (g >> 2) & 127, cg = g & 3;
        if (pl == 0) {
            cp16(smb + 2 * (stage * G_STG + r * 40 + cg * 8),
                 Ah + (size_t)(m0 + r) * KP + k0 + cg * 8);
        } else if (ALO) {
            cp16(smb + 2 * (stage * G_STG + 5120 + r * 40 + cg * 8),
                 Al + (size_t)(m0 + r) * KP + k0 + cg * 8);
        }
    }
#pragma unroll
    for (int it = 0; it < 4; ++it) {
        int g = tid + it * 256;
        int pl = g >> 9, r = (g >> 2) & 127, cg = g & 3;
        const __half* src = (pl ? Bl : Bh) + (size_t)(n0 + r) * KP + k0 + cg * 8;
        cp16(smb + 2 * (stage * G_STG + 10240 + pl * 5120 + r * 40 + cg * 8), src);
    }
}

template <bool ALO>
__global__ __launch_bounds__(256) void gemm_half(
    const __half* __restrict__ Ah, const __half* __restrict__ Al,
    const __half* __restrict__ Bh, const __half* __restrict__ Bl,
    const float* __restrict__ bias, float* __restrict__ C,
    int Ntot, int KP, int H)
{
    const int tid = threadIdx.x;
    const int lane = tid & 31, wid = tid >> 5;
    const int qt = lane & 3, qd = lane >> 2;
    const int n0 = blockIdx.x * 128;
    const int m0 = blockIdx.y * 128;
    const int wm = (wid >> 1) * 32, wn = (wid & 1) * 64;
    const uint32_t smb = smem_u32(hsm);

    float* bs = (float*)(hsm + GS * G_STG);
    if (tid < 128) {
        int n = n0 + tid;
        bs[tid] = (n < Ntot) ? bias[(size_t)(n & 3) * H + (n >> 2)] : 0.0f;
    }

    float acc0[2][8][4] = {}, acc1[2][8][4] = {};
    const int nt = KP / 32;

#pragma unroll
    for (int s = 0; s < GS - 1; ++s) {
        g_load<ALO>(smb, s, Ah, Al, Bh, Bl, m0, n0, KP, s * 32, tid);
        cp_commit();
    }

    for (int i = 0; i < nt; ++i) {
        if (i + GS - 1 < nt)
            g_load<ALO>(smb, (i + GS - 1) % GS, Ah, Al, Bh, Bl, m0, n0, KP, (i + GS - 1) * 32, tid);
        cp_commit();
        cp_wait<GS - 1>();
        __syncthreads();

        const uint32_t sb = smb + 2 * ((i % GS) * G_STG);
#pragma unroll
        for (int s = 0; s < 2; ++s) {
            const int k0 = s * 16;
            uint32_t afh[2][4], afl[2][4];
#pragma unroll
            for (int mt = 0; mt < 2; ++mt) {
                uint32_t arow = wm + mt * 16 + (lane & 15);
                uint32_t acol = k0 + (lane >> 4) * 8;
                ldsm4(afh[mt], sb + 2 * (arow * 40 + acol));
                if (ALO) ldsm4(afl[mt], sb + 2 * (5120u + arow * 40 + acol));
            }
#pragma unroll
            for (int gp = 0; gp < 4; ++gp) {
                uint32_t brow = wn + gp * 16 + ((lane >> 4) & 1) * 8 + (lane & 7);
                uint32_t bcol = k0 + ((lane >> 3) & 1) * 8;
                uint32_t tb[4], tl[4];
                ldsm4(tb, sb + 2 * (10240u + brow * 40 + bcol));
                ldsm4(tl, sb + 2 * (15360u + brow * 40 + bcol));
#pragma unroll
                for (int mt = 0; mt < 2; ++mt)
#pragma unroll
                    for (int j = 0; j < 2; ++j) {
                        int ntl = gp * 2 + j;
                        mma_h(acc0[mt][ntl], afh[mt], tb[j * 2], tb[j * 2 + 1]);
                        mma_h(acc1[mt][ntl], afh[mt], tl[j * 2], tl[j * 2 + 1]);
                        if (ALO) mma_h(acc1[mt][ntl], afl[mt], tb[j * 2], tb[j * 2 + 1]);
                    }
            }
        }
        __syncthreads();
    }

#pragma unroll
    for (int mt = 0; mt < 2; ++mt) {
        int row = m0 + wm + mt * 16 + qd;
#pragma unroll
        for (int ntl = 0; ntl < 8; ++ntl) {
            int cl = wn + ntl * 8 + 2 * qt;
            int col = n0 + cl;
            if (col < Ntot) {
                float b0 = bs[cl], b1 = bs[cl + 1];
                float2 v0, v1;
                v0.x = acc0[mt][ntl][0] + acc1[mt][ntl][0] * INV2048 + b0;
                v0.y = acc0[mt][ntl][1] + acc1[mt][ntl][1] * INV2048 + b1;
                v1.x = acc0[mt][ntl][2] + acc1[mt][ntl][2] * INV2048 + b0;
                v1.y = acc0[mt][ntl][3] + acc1[mt][ntl][3] * INV2048 + b1;
                *(float2*)(C + (size_t)row * Ntot + col) = v0;
                *(float2*)(C + (size_t)(row + 8) * Ntot + col) = v1;
            }
        }
    }
}

// ===========================================================================
// lstm_persist: all timesteps of one layer, weights SMEM-resident.
// A (h state) = single fp16 plane; W split hi/lo (2 mma/tile).
// K-chunk 128, 2 stages; flag-array grid barrier.
// SMEM (halves): WH[32][WSTR] | WL[32][WSTR] | stages[2][A 128x136]
// ===========================================================================
#define LKC 128
#define LSTG 17408u   // halves per stage (128 x 136)

__global__ __launch_bounds__(256) void lstm_persist(
    const float* __restrict__ xg,     // [T][B][Ntot]
    __half* __restrict__ ah,          // [T+1][B][KP]
    const __half* __restrict__ wH, const __half* __restrict__ wL,
    float* __restrict__ out,          // [T][B][H]
    unsigned* __restrict__ flags,
    int H, int KP)
{
    const int Ntot = 4 * H;
    const int WSTR = KP + 8;
    const int tid = threadIdx.x;
    const int lane = tid & 31, wid = tid >> 5;
    const int qt = lane & 3, qd = lane >> 2;
    const int n0 = blockIdx.x * 32;
    const int wm = (wid >> 1) * 32, wn = (wid & 1) * 16;
    const uint32_t smb = smem_u32(hsm);
    const uint32_t SOFF = 64u * (uint32_t)WSTR;   // stage base (halves)
    const int nt = KP / LKC;
    const unsigned nCTA = gridDim.x;
    unsigned* gow = flags + 256;

    // ---- preload weight tile (rows n0..n0+31, hi+lo) into SMEM ----
    {
        const int kops = KP / 8;
        for (int i = tid; i < 32 * kops; i += 256) {
            int r = i / kops, c = (i - r * kops) * 8;
            cp16(smb + 2 * (uint32_t)(r * WSTR + c), wH + (size_t)(n0 + r) * KP + c);
            cp16(smb + 2 * (uint32_t)((32 + r) * WSTR + c), wL + (size_t)(n0 + r) * KP + c);
        }
        cp_commit();
        cp_wait<0>();
        __syncthreads();
    }

    float c4[4] = {0.f, 0.f, 0.f, 0.f};
    const int b = wm + lane;
    const int nbase = n0 + wn;

#define PL_LOAD(STAGE, K0)                                                    \
    {                                                                         \
        _Pragma("unroll")                                                     \
        for (int it = 0; it < 8; ++it) {                                      \
            int g = tid + it * 256;                                           \
            int r = g >> 4, cg = g & 15;                                      \
            cp16(smb + 2 * (SOFF + (STAGE) * LSTG + r * 136u + cg * 8u),      \
                 hH + (size_t)r * KP + (K0) + cg * 8);                        \
        }                                                                     \
    }

    for (int t = 0; t < T_SEQ; ++t) {
        const __half* hH = ah + (size_t)t * BATCH * KP;

        float acc0[2][2][4] = {}, acc1[2][2][4] = {};

        PL_LOAD(0, 0);
        cp_commit();

        for (int i = 0; i < nt; ++i) {
            if (i + 1 < nt) PL_LOAD((i + 1) & 1, (i + 1) * LKC);
            cp_commit();
            cp_wait<1>();
            __syncthreads();

            const uint32_t sa = smb + 2 * (SOFF + (uint32_t)(i & 1) * LSTG);
            const int kb = i * LKC;
#pragma unroll
            for (int s = 0; s < 8; ++s) {
                const int k0 = s * 16;
                uint32_t afh[2][4];
#pragma unroll
                for (int mt = 0; mt < 2; ++mt) {
                    uint32_t arow = wm + mt * 16 + (lane & 15);
                    uint32_t acol = k0 + (lane >> 4) * 8;
                    ldsm4(afh[mt], sa + 2 * (arow * 136 + acol));
                }
                uint32_t bh[2][2], bl[2][2];
                {
                    uint32_t brow = wn + ((lane >> 4) & 1) * 8 + (lane & 7);
                    uint32_t bcol = (uint32_t)(kb + k0) + ((lane >> 3) & 1) * 8;
                    uint32_t t4[4];
                    ldsm4(t4, smb + 2 * (brow * (uint32_t)WSTR + bcol));
                    bh[0][0] = t4[0]; bh[0][1] = t4[1]; bh[1][0] = t4[2]; bh[1][1] = t4[3];
                    ldsm4(t4, smb + 2 * ((brow + 32u) * (uint32_t)WSTR + bcol));
                    bl[0][0] = t4[0]; bl[0][1] = t4[1]; bl[1][0] = t4[2]; bl[1][1] = t4[3];
                }
#pragma unroll
                for (int mt = 0; mt < 2; ++mt)
#pragma unroll
                    for (int ntl = 0; ntl < 2; ++ntl) {
                        mma_h(acc0[mt][ntl], afh[mt], bh[ntl][0], bh[ntl][1]);
                        mma_h(acc1[mt][ntl], afh[mt], bl[ntl][0], bl[ntl][1]);
                    }
            }
            __syncthreads();
        }

        // ---- gate epilogue (overlay on stage region; stages idle) ----
        float* gsm = (float*)(hsm + SOFF) + wid * (32 * 20);
#pragma unroll
        for (int mt = 0; mt < 2; ++mt)
#pragma unroll
            for (int ntl = 0; ntl < 2; ++ntl) {
                int r0 = mt * 16 + qd;
                int c0 = ntl * 8 + 2 * qt;
                gsm[r0 * 20 + c0]           = acc0[mt][ntl][0] + acc1[mt][ntl][0] * INV2048;
                gsm[r0 * 20 + c0 + 1]       = acc0[mt][ntl][1] + acc1[mt][ntl][1] * INV2048;
                gsm[(r0 + 8) * 20 + c0]     = acc0[mt][ntl][2] + acc1[mt][ntl][2] * INV2048;
                gsm[(r0 + 8) * 20 + c0 + 1] = acc0[mt][ntl][3] + acc1[mt][ntl][3] * INV2048;
            }
        __syncwarp();

        __half* nH = ah + (size_t)(t + 1) * BATCH * KP;
        const float* xgb = xg + ((size_t)t * BATCH + b) * Ntot;
        float* ob = out + ((size_t)t * BATCH + b) * H;
#pragma unroll
        for (int u = 0; u < 4; ++u) {
            int colg = nbase + 4 * u;
            if (colg < Ntot) {
                int j = colg >> 2;
                float4 g4 = *(float4*)&gsm[lane * 20 + 4 * u];
                float4 x4 = *(const float4*)(xgb + colg);
                float pi = g4.x + x4.x;
                float pf = g4.y + x4.y;
                float pg = g4.z + x4.z;
                float po = g4.w + x4.w;
                float cc = sigm(pf) * c4[u] + sigm(pi) * tanhf(pg);
                c4[u] = cc;
                float h = sigm(po) * tanhf(cc);
                ob[j] = h;
                nH[(size_t)b * KP + j] = __float2half_rn(h);
            }
        }

        // ---- flag-array grid barrier ----
        __threadfence();
        __syncthreads();
        const unsigned epoch = (unsigned)(t + 1);
        if (tid == 0) st_rel(flags + blockIdx.x, epoch);
        if (blockIdx.x == 0) {
            if (tid < nCTA) {
                while (ld_acq(flags + tid) < epoch) __nanosleep(32);
            }
            __syncthreads();
            if (tid == 0) st_rel(gow, epoch);
        } else {
            if (tid == 0) {
                while (ld_acq(gow) < epoch) __nanosleep(32);
            }
            __syncthreads();
        }
    }
#undef PL_LOAD
}

// ---------------------------------------------------------------------------
extern "C" void kernel_launch(void* const* d_in, const int* in_sizes, int n_in,
                              void* d_out, int out_size) {
    const int*   tokens = (const int*)d_in[0];
    const float* emb    = (const float*)d_in[1];
    const float* Wih[3] = {(const float*)d_in[2], (const float*)d_in[5], (const float*)d_in[8]};
    const float* Whh[3] = {(const float*)d_in[3], (const float*)d_in[6], (const float*)d_in[9]};
    const float* bb[3]  = {(const float*)d_in[4], (const float*)d_in[7], (const float*)d_in[10]};
    float* out = (float*)d_out;

    float *xg;
    __half *ah, *al, *wbh, *wbl;
    unsigned* flags;
    cudaGetSymbolAddress((void**)&xg,  g_xg);
    cudaGetSymbolAddress((void**)&ah,  g_ah);
    cudaGetSymbolAddress((void**)&al,  g_al);
    cudaGetSymbolAddress((void**)&wbh, g_wbh);
    cudaGetSymbolAddress((void**)&wbl, g_wbl);
    cudaGetSymbolAddress((void**)&flags, g_flags);

    const int PSMEM_MAX = (64 * (1152 + 8) + 2 * (int)LSTG) * 2;  // 218112
    cudaFuncSetAttribute(gemm_half<true>,  cudaFuncAttributeMaxDynamicSharedMemorySize, GEMM_SMEM);
    cudaFuncSetAttribute(gemm_half<false>, cudaFuncAttributeMaxDynamicSharedMemorySize, GEMM_SMEM);
    cudaFuncSetAttribute(lstm_persist, cudaFuncAttributeMaxDynamicSharedMemorySize, PSMEM_MAX);

    embed_split<<<MROWS, 128>>>(tokens, emb, ah, al);

    const int Hs[3]   = {1150, 1150, 400};
    const int Kin[3]  = {400, 1150, 1150};
    const int KPin[3] = {416, 1152, 1152};
    const int HPs[3]  = {1152, 1152, 512};   // recurrent K padded to x128
    const size_t outoff[3] = {0, (size_t)MROWS * 1150, (size_t)MROWS * 1150 * 2};

    for (int l = 0; l < 3; ++l) {
        const int H = Hs[l], K = Kin[l], KP = KPin[l], HP = HPs[l], N = 4 * H;

        // input-weight planes + GEMM for xg
        split_w<<<(4 * H * KP + 255) / 256, 256>>>(Wih[l], wbh, wbl, H, K, KP);
        const __half* Asrc_h = (l == 0) ? ah : (ah + (size_t)BATCH * 1152);
        dim3 gg((N + 127) / 128, MROWS / 128);
        if (l == 0)
            gemm_half<true><<<gg, 256, GEMM_SMEM>>>(Asrc_h, al, wbh, wbl, bb[l], xg, N, KP, H);
        else
            gemm_half<false><<<gg, 256, GEMM_SMEM>>>(Asrc_h, (const __half*)nullptr,
                                                     wbh, wbl, bb[l], xg, N, KP, H);

        // reset h-plane buffer (zeroes slot 0 and pad cols) + barrier flags
        cudaMemsetAsync(ah, 0, (size_t)(T_SEQ + 1) * BATCH * HP * 2);
        cudaMemsetAsync(flags, 0, 512 * sizeof(unsigned));

        // recurrent-weight planes
        split_w<<<(4 * H * HP + 255) / 256, 256>>>(Whh[l], wbh, wbl, H, H, HP);

        // persistent recurrent kernel: all 200 steps in one launch
        const int nblk = (N + 31) / 32;   // 144 or 50
        const int psm = (64 * (HP + 8) + 2 * (int)LSTG) * 2;
        lstm_persist<<<nblk, 256, psm>>>(xg, ah, wbh, wbl,
                                         out + outoff[l], flags, H, HP);
    }
}

// round 10
// speedup vs baseline: 5.1404x; 1.3381x over previous
#include <cuda_runtime.h>
#include <cuda_fp16.h>
#include <math.h>
#include <stdint.h>

#define T_SEQ 200
#define BATCH 128
#define MROWS (T_SEQ * BATCH)   // 25600

// ---- device-global scratch ----
__device__ float  g_xg[(size_t)MROWS * 4600];
__device__ __half g_ah[(size_t)(T_SEQ + 1) * BATCH * 1152];  // A / h plane (fp16)
__device__ __half g_wbh[(size_t)4608 * 1152];                // weight plane (fp16)
__device__ unsigned g_flags[512];                            // CTA flags + go-word

// ===========================================================================
// PTX helpers (sm_80-era, safe on plain sm_103 target)
// ===========================================================================
__device__ __forceinline__ uint32_t smem_u32(const void* p) {
    uint32_t a;
    asm("{ .reg .u64 t; cvta.to.shared.u64 t, %1; cvt.u32.u64 %0, t; }" : "=r"(a) : "l"(p));
    return a;
}
__device__ __forceinline__ void cp16(uint32_t s, const void* g) {
    asm volatile("cp.async.cg.shared.global [%0], [%1], 16;" :: "r"(s), "l"(g));
}
__device__ __forceinline__ void cp_commit() {
    asm volatile("cp.async.commit_group;");
}
template <int N> __device__ __forceinline__ void cp_wait() {
    asm volatile("cp.async.wait_group %0;" :: "n"(N));
}
__device__ __forceinline__ void ldsm4(uint32_t* r, uint32_t a) {
    asm volatile("ldmatrix.sync.aligned.m8n8.x4.shared.b16 {%0,%1,%2,%3}, [%4];"
        : "=r"(r[0]), "=r"(r[1]), "=r"(r[2]), "=r"(r[3]) : "r"(a));
}
__device__ __forceinline__ void mma_h(float* d, const uint32_t* a, uint32_t b0, uint32_t b1) {
    asm volatile("mma.sync.aligned.m16n8k16.row.col.f32.f16.f16.f32 "
        "{%0,%1,%2,%3}, {%4,%5,%6,%7}, {%8,%9}, {%0,%1,%2,%3};"
        : "+f"(d[0]), "+f"(d[1]), "+f"(d[2]), "+f"(d[3])
        : "r"(a[0]), "r"(a[1]), "r"(a[2]), "r"(a[3]), "r"(b0), "r"(b1));
}
__device__ __forceinline__ void st_rel(unsigned* p, unsigned v) {
    asm volatile("st.global.release.gpu.u32 [%0], %1;" :: "l"(p), "r"(v) : "memory");
}
__device__ __forceinline__ unsigned ld_acq(const unsigned* p) {
    unsigned v;
    asm volatile("ld.global.acquire.gpu.u32 %0, [%1];" : "=r"(v) : "l"(p) : "memory");
    return v;
}
__device__ __forceinline__ float sigm(float x) { return 1.0f / (1.0f + expf(-x)); }

// ===========================================================================
// Pre-convert kernels
// ===========================================================================
__global__ void embed_split(const int* __restrict__ tokens,
                            const float* __restrict__ emb,
                            __half* __restrict__ ah) {
    int row = blockIdx.x;
    int tok = tokens[row];
    const float* src = emb + (size_t)tok * 400;
    __half* dh = ah + (size_t)row * 416;
    for (int i = threadIdx.x; i < 416; i += blockDim.x) {
        float v = (i < 400) ? src[i] : 0.0f;
        dh[i] = __float2half_rn(v);
    }
}

// convert + gate-permute weights: out row n = (4j+g) <- src row (g*H+j); pad k>=K
__global__ void split_w(const float* __restrict__ W,
                        __half* __restrict__ bh,
                        int H, int K, int KP) {
    int id = blockIdx.x * 256 + threadIdx.x;
    int total = 4 * H * KP;
    if (id >= total) return;
    int n = id / KP, k = id - n * KP;
    float v = (k < K) ? W[(size_t)((n & 3) * H + (n >> 2)) * K + k] : 0.0f;
    bh[id] = __float2half_rn(v);
}

// ===========================================================================
// gemm_half: xg = A @ Wperm^T + biasperm (pure fp16 operands, fp32 acc).
// CTA 128x128, 8 warps (32x64), K-chunk 32, 3-stage cp.async.
// Stage (halves): A[128][40] | B[128][40]
// ===========================================================================
#define GS 3
#define G_STG 10240
#define GEMM_SMEM (GS * G_STG * 2 + 512)

extern __shared__ __half hsm[];

__device__ __forceinline__ void g_load(uint32_t smb, int stage,
    const __half* __restrict__ Ah, const __half* __restrict__ Bh,
    int m0, int n0, int KP, int k0, int tid)
{
#pragma unroll
    for (int it = 0; it < 2; ++it) {
        int g = tid + it * 256;
        int r = g >> 2, cg = g & 3;
        cp16(smb + 2 * (stage * G_STG + r * 40 + cg * 8),
             Ah + (size_t)(m0 + r) * KP + k0 + cg * 8);
    }
#pragma unroll
    for (int it = 0; it < 2; ++it) {
        int g = tid + it * 256;
        int r = g >> 2, cg = g & 3;
        cp16(smb + 2 * (stage * G_STG + 5120 + r * 40 + cg * 8),
             Bh + (size_t)(n0 + r) * KP + k0 + cg * 8);
    }
}

__global__ __launch_bounds__(256) void gemm_half(
    const __half* __restrict__ Ah, const __half* __restrict__ Bh,
    const float* __restrict__ bias, float* __restrict__ C,
    int Ntot, int KP, int H)
{
    const int tid = threadIdx.x;
    const int lane = tid & 31, wid = tid >> 5;
    const int qt = lane & 3, qd = lane >> 2;
    const int n0 = blockIdx.x * 128;
    const int m0 = blockIdx.y * 128;
    const int wm = (wid >> 1) * 32, wn = (wid & 1) * 64;
    const uint32_t smb = smem_u32(hsm);

    float* bs = (float*)(hsm + GS * G_STG);
    if (tid < 128) {
        int n = n0 + tid;
        bs[tid] = (n < Ntot) ? bias[(size_t)(n & 3) * H + (n >> 2)] : 0.0f;
    }

    float acc[2][8][4] = {};
    const int nt = KP / 32;

#pragma unroll
    for (int s = 0; s < GS - 1; ++s) {
        g_load(smb, s, Ah, Bh, m0, n0, KP, s * 32, tid);
        cp_commit();
    }

    for (int i = 0; i < nt; ++i) {
        if (i + GS - 1 < nt)
            g_load(smb, (i + GS - 1) % GS, Ah, Bh, m0, n0, KP, (i + GS - 1) * 32, tid);
        cp_commit();
        cp_wait<GS - 1>();
        __syncthreads();

        const uint32_t sb = smb + 2 * ((i % GS) * G_STG);
#pragma unroll
        for (int s = 0; s < 2; ++s) {
            const int k0 = s * 16;
            uint32_t af[2][4];
#pragma unroll
            for (int mt = 0; mt < 2; ++mt) {
                uint32_t arow = wm + mt * 16 + (lane & 15);
                uint32_t acol = k0 + (lane >> 4) * 8;
                ldsm4(af[mt], sb + 2 * (arow * 40 + acol));
            }
#pragma unroll
            for (int gp = 0; gp < 4; ++gp) {
                uint32_t brow = wn + gp * 16 + ((lane >> 4) & 1) * 8 + (lane & 7);
                uint32_t bcol = k0 + ((lane >> 3) & 1) * 8;
                uint32_t tb[4];
                ldsm4(tb, sb + 2 * (5120u + brow * 40 + bcol));
#pragma unroll
                for (int mt = 0; mt < 2; ++mt)
#pragma unroll
                    for (int j = 0; j < 2; ++j)
                        mma_h(acc[mt][gp * 2 + j], af[mt], tb[j * 2], tb[j * 2 + 1]);
            }
        }
        __syncthreads();
    }

#pragma unroll
    for (int mt = 0; mt < 2; ++mt) {
        int row = m0 + wm + mt * 16 + qd;
#pragma unroll
        for (int ntl = 0; ntl < 8; ++ntl) {
            int cl = wn + ntl * 8 + 2 * qt;
            int col = n0 + cl;
            if (col < Ntot) {
                float b0 = bs[cl], b1 = bs[cl + 1];
                float2 v0 = make_float2(acc[mt][ntl][0] + b0, acc[mt][ntl][1] + b1);
                float2 v1 = make_float2(acc[mt][ntl][2] + b0, acc[mt][ntl][3] + b1);
                *(float2*)(C + (size_t)row * Ntot + col) = v0;
                *(float2*)(C + (size_t)(row + 8) * Ntot + col) = v1;
            }
        }
    }
}

// ===========================================================================
// lstm_persist: all timesteps of one layer; fp16 weights SMEM-resident
// (32 rows), fp16 h state, 1 mma per tile. K-chunk 128, 2 stages.
// SMEM (halves): W[32][WSTR] | stages[2][A 128x136]
// ===========================================================================
#define LKC 128
#define LSTG 17408u   // halves per stage (128 x 136)

__global__ __launch_bounds__(256) void lstm_persist(
    const float* __restrict__ xg,     // [T][B][Ntot]
    __half* __restrict__ ah,          // [T+1][B][KP]
    const __half* __restrict__ wH,
    float* __restrict__ out,          // [T][B][H]
    unsigned* __restrict__ flags,
    int H, int KP)
{
    const int Ntot = 4 * H;
    const int WSTR = KP + 8;
    const int tid = threadIdx.x;
    const int lane = tid & 31, wid = tid >> 5;
    const int qt = lane & 3, qd = lane >> 2;
    const int n0 = blockIdx.x * 32;
    const int wm = (wid >> 1) * 32, wn = (wid & 1) * 16;
    const uint32_t smb = smem_u32(hsm);
    const uint32_t SOFF = 32u * (uint32_t)WSTR;   // stage base (halves)
    const int nt = KP / LKC;
    const unsigned nCTA = gridDim.x;
    unsigned* gow = flags + 256;

    // ---- preload weight tile (rows n0..n0+31) into SMEM ----
    {
        const int kops = KP / 8;
        for (int i = tid; i < 32 * kops; i += 256) {
            int r = i / kops, c = (i - r * kops) * 8;
            cp16(smb + 2 * (uint32_t)(r * WSTR + c), wH + (size_t)(n0 + r) * KP + c);
        }
        cp_commit();
        cp_wait<0>();
        __syncthreads();
    }

    float c4[4] = {0.f, 0.f, 0.f, 0.f};
    const int b = wm + lane;
    const int nbase = n0 + wn;

#define PL_LOAD(STAGE, K0)                                                    \
    {                                                                         \
        _Pragma("unroll")                                                     \
        for (int it = 0; it < 8; ++it) {                                      \
            int g = tid + it * 256;                                           \
            int r = g >> 4, cg = g & 15;                                      \
            cp16(smb + 2 * (SOFF + (STAGE) * LSTG + r * 136u + cg * 8u),      \
                 hH + (size_t)r * KP + (K0) + cg * 8);                        \
        }                                                                     \
    }

    for (int t = 0; t < T_SEQ; ++t) {
        const __half* hH = ah + (size_t)t * BATCH * KP;

        float acc[2][2][4] = {};

        PL_LOAD(0, 0);
        cp_commit();

        for (int i = 0; i < nt; ++i) {
            if (i + 1 < nt) PL_LOAD((i + 1) & 1, (i + 1) * LKC);
            cp_commit();
            cp_wait<1>();
            __syncthreads();

            const uint32_t sa = smb + 2 * (SOFF + (uint32_t)(i & 1) * LSTG);
            const int kb = i * LKC;
#pragma unroll
            for (int s = 0; s < 8; ++s) {
                const int k0 = s * 16;
                uint32_t af[2][4];
#pragma unroll
                for (int mt = 0; mt < 2; ++mt) {
                    uint32_t arow = wm + mt * 16 + (lane & 15);
                    uint32_t acol = k0 + (lane >> 4) * 8;
                    ldsm4(af[mt], sa + 2 * (arow * 136 + acol));
                }
                uint32_t bh[2][2];
                {
                    uint32_t brow = wn + ((lane >> 4) & 1) * 8 + (lane & 7);
                    uint32_t bcol = (uint32_t)(kb + k0) + ((lane >> 3) & 1) * 8;
                    uint32_t t4[4];
                    ldsm4(t4, smb + 2 * (brow * (uint32_t)WSTR + bcol));
                    bh[0][0] = t4[0]; bh[0][1] = t4[1]; bh[1][0] = t4[2]; bh[1][1] = t4[3];
                }
#pragma unroll
                for (int mt = 0; mt < 2; ++mt)
#pragma unroll
                    for (int ntl = 0; ntl < 2; ++ntl)
                        mma_h(acc[mt][ntl], af[mt], bh[ntl][0], bh[ntl][1]);
            }
            __syncthreads();
        }

        // ---- gate epilogue (overlay on stage region; stages idle) ----
        float* gsm = (float*)(hsm + SOFF) + wid * (32 * 20);
#pragma unroll
        for (int mt = 0; mt < 2; ++mt)
#pragma unroll
            for (int ntl = 0; ntl < 2; ++ntl) {
                int r0 = mt * 16 + qd;
                int c0 = ntl * 8 + 2 * qt;
                gsm[r0 * 20 + c0]           = acc[mt][ntl][0];
                gsm[r0 * 20 + c0 + 1]       = acc[mt][ntl][1];
                gsm[(r0 + 8) * 20 + c0]     = acc[mt][ntl][2];
                gsm[(r0 + 8) * 20 + c0 + 1] = acc[mt][ntl][3];
            }
        __syncwarp();

        __half* nH = ah + (size_t)(t + 1) * BATCH * KP;
        const float* xgb = xg + ((size_t)t * BATCH + b) * Ntot;
        float* ob = out + ((size_t)t * BATCH + b) * H;
#pragma unroll
        for (int u = 0; u < 4; ++u) {
            int colg = nbase + 4 * u;
            if (colg < Ntot) {
                int j = colg >> 2;
                float4 g4 = *(float4*)&gsm[lane * 20 + 4 * u];
                float4 x4 = *(const float4*)(xgb + colg);
                float pi = g4.x + x4.x;
                float pf = g4.y + x4.y;
                float pg = g4.z + x4.z;
                float po = g4.w + x4.w;
                float cc = sigm(pf) * c4[u] + sigm(pi) * tanhf(pg);
                c4[u] = cc;
                float h = sigm(po) * tanhf(cc);
                ob[j] = h;
                nH[(size_t)b * KP + j] = __float2half_rn(h);
            }
        }

        // ---- flag-array grid barrier ----
        __threadfence();
        __syncthreads();
        const unsigned epoch = (unsigned)(t + 1);
        if (tid == 0) st_rel(flags + blockIdx.x, epoch);
        if (blockIdx.x == 0) {
            if (tid < nCTA) {
                while (ld_acq(flags + tid) < epoch) __nanosleep(32);
            }
            __syncthreads();
            if (tid == 0) st_rel(gow, epoch);
        } else {
            if (tid == 0) {
                while (ld_acq(gow) < epoch) __nanosleep(32);
            }
            __syncthreads();
        }
    }
#undef PL_LOAD
}

// ---------------------------------------------------------------------------
extern "C" void kernel_launch(void* const* d_in, const int* in_sizes, int n_in,
                              void* d_out, int out_size) {
    const int*   tokens = (const int*)d_in[0];
    const float* emb    = (const float*)d_in[1];
    const float* Wih[3] = {(const float*)d_in[2], (const float*)d_in[5], (const float*)d_in[8]};
    const float* Whh[3] = {(const float*)d_in[3], (const float*)d_in[6], (const float*)d_in[9]};
    const float* bb[3]  = {(const float*)d_in[4], (const float*)d_in[7], (const float*)d_in[10]};
    float* out = (float*)d_out;

    float *xg;
    __half *ah, *wbh;
    unsigned* flags;
    cudaGetSymbolAddress((void**)&xg,  g_xg);
    cudaGetSymbolAddress((void**)&ah,  g_ah);
    cudaGetSymbolAddress((void**)&wbh, g_wbh);
    cudaGetSymbolAddress((void**)&flags, g_flags);

    const int PSMEM_MAX = (32 * (1152 + 8) + 2 * (int)LSTG) * 2;  // 143872
    cudaFuncSetAttribute(gemm_half,    cudaFuncAttributeMaxDynamicSharedMemorySize, GEMM_SMEM);
    cudaFuncSetAttribute(lstm_persist, cudaFuncAttributeMaxDynamicSharedMemorySize, PSMEM_MAX);

    embed_split<<<MROWS, 128>>>(tokens, emb, ah);

    const int Hs[3]   = {1150, 1150, 400};
    const int Kin[3]  = {400, 1150, 1150};
    const int KPin[3] = {416, 1152, 1152};
    const int HPs[3]  = {1152, 1152, 512};   // recurrent K padded to x128
    const size_t outoff[3] = {0, (size_t)MROWS * 1150, (size_t)MROWS * 1150 * 2};

    for (int l = 0; l < 3; ++l) {
        const int H = Hs[l], K = Kin[l], KP = KPin[l], HP = HPs[l], N = 4 * H;

        // input-weight plane + GEMM for xg
        split_w<<<(4 * H * KP + 255) / 256, 256>>>(Wih[l], wbh, H, K, KP);
        const __half* Asrc = (l == 0) ? ah : (ah + (size_t)BATCH * 1152);
        dim3 gg((N + 127) / 128, MROWS / 128);
        gemm_half<<<gg, 256, GEMM_SMEM>>>(Asrc, wbh, bb[l], xg, N, KP, H);

        // reset h-plane buffer (zeroes slot 0 and pad cols) + barrier flags
        cudaMemsetAsync(ah, 0, (size_t)(T_SEQ + 1) * BATCH * HP * 2);
        cudaMemsetAsync(flags, 0, 512 * sizeof(unsigned));

        // recurrent-weight plane
        split_w<<<(4 * H * HP + 255) / 256, 256>>>(Whh[l], wbh, H, H, HP);

        // persistent recurrent kernel: all 200 steps in one launch
        const int nblk = (N + 31) / 32;   // 144 or 50
        const int psm = (32 * (HP + 8) + 2 * (int)LSTG) * 2;
        lstm_persist<<<nblk, 256, psm>>>(xg, ah, wbh,
                                         out + outoff[l], flags, H, HP);
    }
}

// round 11
// speedup vs baseline: 5.3455x; 1.0399x over previous
#include <cuda_runtime.h>
#include <cuda_fp16.h>
#include <math.h>
#include <stdint.h>

#define T_SEQ 200
#define BATCH 128
#define MROWS (T_SEQ * BATCH)   // 25600

// ---- device-global scratch ----
__device__ float  g_xg[(size_t)MROWS * 4600];
__device__ __half g_ah[(size_t)(T_SEQ + 1) * BATCH * 1152];  // A / h plane (fp16)
__device__ __half g_wbh[(size_t)4608 * 1152];                // weight plane (fp16)
__device__ unsigned g_flags[512];                            // CTA flags + go-word

// ===========================================================================
// PTX helpers (sm_80-era, safe on plain sm_103 target)
// ===========================================================================
__device__ __forceinline__ uint32_t smem_u32(const void* p) {
    uint32_t a;
    asm("{ .reg .u64 t; cvta.to.shared.u64 t, %1; cvt.u32.u64 %0, t; }" : "=r"(a) : "l"(p));
    return a;
}
__device__ __forceinline__ void cp16(uint32_t s, const void* g) {
    asm volatile("cp.async.cg.shared.global [%0], [%1], 16;" :: "r"(s), "l"(g));
}
__device__ __forceinline__ void cp_commit() {
    asm volatile("cp.async.commit_group;");
}
template <int N> __device__ __forceinline__ void cp_wait() {
    asm volatile("cp.async.wait_group %0;" :: "n"(N));
}
__device__ __forceinline__ void ldsm4(uint32_t* r, uint32_t a) {
    asm volatile("ldmatrix.sync.aligned.m8n8.x4.shared.b16 {%0,%1,%2,%3}, [%4];"
        : "=r"(r[0]), "=r"(r[1]), "=r"(r[2]), "=r"(r[3]) : "r"(a));
}
__device__ __forceinline__ void mma_h(float* d, const uint32_t* a, uint32_t b0, uint32_t b1) {
    asm volatile("mma.sync.aligned.m16n8k16.row.col.f32.f16.f16.f32 "
        "{%0,%1,%2,%3}, {%4,%5,%6,%7}, {%8,%9}, {%0,%1,%2,%3};"
        : "+f"(d[0]), "+f"(d[1]), "+f"(d[2]), "+f"(d[3])
        : "r"(a[0]), "r"(a[1]), "r"(a[2]), "r"(a[3]), "r"(b0), "r"(b1));
}
__device__ __forceinline__ void st_rel(unsigned* p, unsigned v) {
    asm volatile("st.global.release.gpu.u32 [%0], %1;" :: "l"(p), "r"(v) : "memory");
}
__device__ __forceinline__ unsigned ld_acq(const unsigned* p) {
    unsigned v;
    asm volatile("ld.global.acquire.gpu.u32 %0, [%1];" : "=r"(v) : "l"(p) : "memory");
    return v;
}
__device__ __forceinline__ float sigm(float x) { return 1.0f / (1.0f + expf(-x)); }

// ===========================================================================
// Pre-convert kernels
// ===========================================================================
__global__ void embed_split(const int* __restrict__ tokens,
                            const float* __restrict__ emb,
                            __half* __restrict__ ah) {
    int row = blockIdx.x;
    int tok = tokens[row];
    const float* src = emb + (size_t)tok * 400;
    __half* dh = ah + (size_t)row * 416;
    for (int i = threadIdx.x; i < 416; i += blockDim.x) {
        float v = (i < 400) ? src[i] : 0.0f;
        dh[i] = __float2half_rn(v);
    }
}

// convert + gate-permute weights: out row n = (4j+g) <- src row (g*H+j); pad k>=K
__global__ void split_w(const float* __restrict__ W,
                        __half* __restrict__ bh,
                        int H, int K, int KP) {
    int id = blockIdx.x * 256 + threadIdx.x;
    int total = 4 * H * KP;
    if (id >= total) return;
    int n = id / KP, k = id - n * KP;
    float v = (k < K) ? W[(size_t)((n & 3) * H + (n >> 2)) * K + k] : 0.0f;
    bh[id] = __float2half_rn(v);
}

// ===========================================================================
// gemm_half: xg = A @ Wperm^T + biasperm (fp16 operands, fp32 acc).
// CTA 128x128, 4 warps (warp 64x64), K-chunk 32, 3-stage cp.async.
// Stage (halves): A[128][40] | B[128][40].  2 CTAs/SM.
// ===========================================================================
#define GS 3
#define G_STG 10240
#define GEMM_SMEM (GS * G_STG * 2 + 512)

extern __shared__ __half hsm[];

__device__ __forceinline__ void g_load(uint32_t smb, int stage,
    const __half* __restrict__ Ah, const __half* __restrict__ Bh,
    int m0, int n0, int KP, int k0, int tid)
{
#pragma unroll
    for (int it = 0; it < 4; ++it) {
        int g = tid + it * 128;
        int r = g >> 2, cg = g & 3;
        cp16(smb + 2 * (stage * G_STG + r * 40 + cg * 8),
             Ah + (size_t)(m0 + r) * KP + k0 + cg * 8);
    }
#pragma unroll
    for (int it = 0; it < 4; ++it) {
        int g = tid + it * 128;
        int r = g >> 2, cg = g & 3;
        cp16(smb + 2 * (stage * G_STG + 5120 + r * 40 + cg * 8),
             Bh + (size_t)(n0 + r) * KP + k0 + cg * 8);
    }
}

__global__ __launch_bounds__(128) void gemm_half(
    const __half* __restrict__ Ah, const __half* __restrict__ Bh,
    const float* __restrict__ bias, float* __restrict__ C,
    int Ntot, int KP, int H)
{
    const int tid = threadIdx.x;
    const int lane = tid & 31, wid = tid >> 5;
    const int qt = lane & 3, qd = lane >> 2;
    const int n0 = blockIdx.x * 128;
    const int m0 = blockIdx.y * 128;
    const int wm = (wid >> 1) * 64, wn = (wid & 1) * 64;
    const uint32_t smb = smem_u32(hsm);

    float* bs = (float*)(hsm + GS * G_STG);
    {
        int n = n0 + tid;
        bs[tid] = (n < Ntot) ? bias[(size_t)(n & 3) * H + (n >> 2)] : 0.0f;
    }

    float acc[4][8][4] = {};
    const int nt = KP / 32;

#pragma unroll
    for (int s = 0; s < GS - 1; ++s) {
        g_load(smb, s, Ah, Bh, m0, n0, KP, s * 32, tid);
        cp_commit();
    }

    for (int i = 0; i < nt; ++i) {
        if (i + GS - 1 < nt)
            g_load(smb, (i + GS - 1) % GS, Ah, Bh, m0, n0, KP, (i + GS - 1) * 32, tid);
        cp_commit();
        cp_wait<GS - 1>();
        __syncthreads();

        const uint32_t sb = smb + 2 * ((i % GS) * G_STG);
#pragma unroll
        for (int s = 0; s < 2; ++s) {
            const int k0 = s * 16;
            uint32_t af[4][4];
#pragma unroll
            for (int mt = 0; mt < 4; ++mt) {
                uint32_t arow = wm + mt * 16 + (lane & 15);
                uint32_t acol = k0 + (lane >> 4) * 8;
                ldsm4(af[mt], sb + 2 * (arow * 40 + acol));
            }
#pragma unroll
            for (int gp = 0; gp < 4; ++gp) {
                uint32_t brow = wn + gp * 16 + ((lane >> 4) & 1) * 8 + (lane & 7);
                uint32_t bcol = k0 + ((lane >> 3) & 1) * 8;
                uint32_t tb[4];
                ldsm4(tb, sb + 2 * (5120u + brow * 40 + bcol));
#pragma unroll
                for (int mt = 0; mt < 4; ++mt)
#pragma unroll
                    for (int j = 0; j < 2; ++j)
                        mma_h(acc[mt][gp * 2 + j], af[mt], tb[j * 2], tb[j * 2 + 1]);
            }
        }
        __syncthreads();
    }

#pragma unroll
    for (int mt = 0; mt < 4; ++mt) {
        int row = m0 + wm + mt * 16 + qd;
#pragma unroll
        for (int ntl = 0; ntl < 8; ++ntl) {
            int cl = wn + ntl * 8 + 2 * qt;
            int col = n0 + cl;
            if (col < Ntot) {
                float b0 = bs[cl], b1 = bs[cl + 1];
                float2 v0 = make_float2(acc[mt][ntl][0] + b0, acc[mt][ntl][1] + b1);
                float2 v1 = make_float2(acc[mt][ntl][2] + b0, acc[mt][ntl][3] + b1);
                *(float2*)(C + (size_t)row * Ntot + col) = v0;
                *(float2*)(C + (size_t)(row + 8) * Ntot + col) = v1;
            }
        }
    }
}

// ===========================================================================
// lstm_persist: all timesteps of one layer; fp16 weights SMEM-resident,
// fp16 h state, 1 mma per tile. K-chunk 128, 2 stages; xg tile prefetched
// into SMEM in the first cp.async group of each step.
// SMEM (halves): W[32][WSTR] | stages[2][A 128x136] | xg[128][36] (fp32)
// ===========================================================================
#define LKC 128
#define LSTG 17408u   // halves per stage (128 x 136)

__global__ __launch_bounds__(256) void lstm_persist(
    const float* __restrict__ xg,     // [T][B][Ntot]
    __half* __restrict__ ah,          // [T+1][B][KP]
    const __half* __restrict__ wH,
    float* __restrict__ out,          // [T][B][H]
    unsigned* __restrict__ flags,
    int H, int KP)
{
    const int Ntot = 4 * H;
    const int WSTR = KP + 8;
    const int tid = threadIdx.x;
    const int lane = tid & 31, wid = tid >> 5;
    const int qt = lane & 3, qd = lane >> 2;
    const int n0 = blockIdx.x * 32;
    const int wm = (wid >> 1) * 32, wn = (wid & 1) * 16;
    const uint32_t smb = smem_u32(hsm);
    const uint32_t SOFF = 32u * (uint32_t)WSTR;        // stage base (halves)
    const uint32_t XOFF = SOFF + 2u * LSTG;            // xg tile base (halves)
    const int nt = KP / LKC;
    const unsigned nCTA = gridDim.x;
    unsigned* gow = flags + 256;

    // ---- preload weight tile (rows n0..n0+31) into SMEM ----
    {
        const int kops = KP / 8;
        for (int i = tid; i < 32 * kops; i += 256) {
            int r = i / kops, c = (i - r * kops) * 8;
            cp16(smb + 2 * (uint32_t)(r * WSTR + c), wH + (size_t)(n0 + r) * KP + c);
        }
        cp_commit();
        cp_wait<0>();
        __syncthreads();
    }

    float c4[4] = {0.f, 0.f, 0.f, 0.f};
    const int b = wm + lane;
    const int nbase = n0 + wn;
    const float* xsm = (const float*)(hsm + XOFF);

#define PL_LOAD(STAGE, K0)                                                    \
    {                                                                         \
        _Pragma("unroll")                                                     \
        for (int it = 0; it < 8; ++it) {                                      \
            int g = tid + it * 256;                                           \
            int r = g >> 4, cg = g & 15;                                      \
            cp16(smb + 2 * (SOFF + (STAGE) * LSTG + r * 136u + cg * 8u),      \
                 hH + (size_t)r * KP + (K0) + cg * 8);                        \
        }                                                                     \
    }

    for (int t = 0; t < T_SEQ; ++t) {
        const __half* hH = ah + (size_t)t * BATCH * KP;
        const float* xgt = xg + (size_t)t * BATCH * Ntot;

        float acc[2][2][4] = {};

        // first group: xg tile (128 x 32 fp32, stride 36) + A chunk 0
        {
#pragma unroll
            for (int it = 0; it < 4; ++it) {
                int g = tid + it * 256;
                int r = g >> 3, c = g & 7;
                int cb = n0 + c * 4;
                if (cb + 4 <= Ntot)
                    cp16(smb + 2 * XOFF + (uint32_t)(r * 144 + c * 16),
                         xgt + (size_t)r * Ntot + cb);
            }
        }
        PL_LOAD(0, 0);
        cp_commit();

        for (int i = 0; i < nt; ++i) {
            if (i + 1 < nt) PL_LOAD((i + 1) & 1, (i + 1) * LKC);
            cp_commit();
            cp_wait<1>();
            __syncthreads();

            const uint32_t sa = smb + 2 * (SOFF + (uint32_t)(i & 1) * LSTG);
            const int kb = i * LKC;
#pragma unroll
            for (int s = 0; s < 8; ++s) {
                const int k0 = s * 16;
                uint32_t af[2][4];
#pragma unroll
                for (int mt = 0; mt < 2; ++mt) {
                    uint32_t arow = wm + mt * 16 + (lane & 15);
                    uint32_t acol = k0 + (lane >> 4) * 8;
                    ldsm4(af[mt], sa + 2 * (arow * 136 + acol));
                }
                uint32_t bh[2][2];
                {
                    uint32_t brow = wn + ((lane >> 4) & 1) * 8 + (lane & 7);
                    uint32_t bcol = (uint32_t)(kb + k0) + ((lane >> 3) & 1) * 8;
                    uint32_t t4[4];
                    ldsm4(t4, smb + 2 * (brow * (uint32_t)WSTR + bcol));
                    bh[0][0] = t4[0]; bh[0][1] = t4[1]; bh[1][0] = t4[2]; bh[1][1] = t4[3];
                }
#pragma unroll
                for (int mt = 0; mt < 2; ++mt)
#pragma unroll
                    for (int ntl = 0; ntl < 2; ++ntl)
                        mma_h(acc[mt][ntl], af[mt], bh[ntl][0], bh[ntl][1]);
            }
            __syncthreads();
        }

        // ---- gate epilogue (gate smem overlays stage region; stages idle) ----
        float* gsm = (float*)(hsm + SOFF) + wid * (32 * 20);
#pragma unroll
        for (int mt = 0; mt < 2; ++mt)
#pragma unroll
            for (int ntl = 0; ntl < 2; ++ntl) {
                int r0 = mt * 16 + qd;
                int c0 = ntl * 8 + 2 * qt;
                gsm[r0 * 20 + c0]           = acc[mt][ntl][0];
                gsm[r0 * 20 + c0 + 1]       = acc[mt][ntl][1];
                gsm[(r0 + 8) * 20 + c0]     = acc[mt][ntl][2];
                gsm[(r0 + 8) * 20 + c0 + 1] = acc[mt][ntl][3];
            }
        __syncwarp();

        __half* nH = ah + (size_t)(t + 1) * BATCH * KP;
        float* ob = out + ((size_t)t * BATCH + b) * H;
#pragma unroll
        for (int u = 0; u < 4; ++u) {
            int colg = nbase + 4 * u;
            if (colg < Ntot) {
                int j = colg >> 2;
                float4 g4 = *(float4*)&gsm[lane * 20 + 4 * u];
                float4 x4 = *(const float4*)&xsm[b * 36 + wn + 4 * u];
                float pi = g4.x + x4.x;
                float pf = g4.y + x4.y;
                float pg = g4.z + x4.z;
                float po = g4.w + x4.w;
                float cc = sigm(pf) * c4[u] + sigm(pi) * tanhf(pg);
                c4[u] = cc;
                float h = sigm(po) * tanhf(cc);
                ob[j] = h;
                nH[(size_t)b * KP + j] = __float2half_rn(h);
            }
        }

        // ---- flag-array grid barrier ----
        __threadfence();
        __syncthreads();
        const unsigned epoch = (unsigned)(t + 1);
        if (tid == 0) st_rel(flags + blockIdx.x, epoch);
        if (blockIdx.x == 0) {
            if (tid < nCTA) {
                while (ld_acq(flags + tid) < epoch) __nanosleep(32);
            }
            __syncthreads();
            if (tid == 0) st_rel(gow, epoch);
        } else {
            if (tid == 0) {
                while (ld_acq(gow) < epoch) __nanosleep(32);
            }
            __syncthreads();
        }
    }
#undef PL_LOAD
}

// ---------------------------------------------------------------------------
extern "C" void kernel_launch(void* const* d_in, const int* in_sizes, int n_in,
                              void* d_out, int out_size) {
    const int*   tokens = (const int*)d_in[0];
    const float* emb    = (const float*)d_in[1];
    const float* Wih[3] = {(const float*)d_in[2], (const float*)d_in[5], (const float*)d_in[8]};
    const float* Whh[3] = {(const float*)d_in[3], (const float*)d_in[6], (const float*)d_in[9]};
    const float* bb[3]  = {(const float*)d_in[4], (const float*)d_in[7], (const float*)d_in[10]};
    float* out = (float*)d_out;

    float *xg;
    __half *ah, *wbh;
    unsigned* flags;
    cudaGetSymbolAddress((void**)&xg,  g_xg);
    cudaGetSymbolAddress((void**)&ah,  g_ah);
    cudaGetSymbolAddress((void**)&wbh, g_wbh);
    cudaGetSymbolAddress((void**)&flags, g_flags);

    const int PSMEM_MAX = (32 * (1152 + 8) + 2 * (int)LSTG) * 2 + 128 * 36 * 4;  // 162304
    cudaFuncSetAttribute(gemm_half,    cudaFuncAttributeMaxDynamicSharedMemorySize, GEMM_SMEM);
    cudaFuncSetAttribute(lstm_persist, cudaFuncAttributeMaxDynamicSharedMemorySize, PSMEM_MAX);

    embed_split<<<MROWS, 128>>>(tokens, emb, ah);

    const int Hs[3]   = {1150, 1150, 400};
    const int Kin[3]  = {400, 1150, 1150};
    const int KPin[3] = {416, 1152, 1152};
    const int HPs[3]  = {1152, 1152, 512};   // recurrent K padded to x128
    const size_t outoff[3] = {0, (size_t)MROWS * 1150, (size_t)MROWS * 1150 * 2};

    for (int l = 0; l < 3; ++l) {
        const int H = Hs[l], K = Kin[l], KP = KPin[l], HP = HPs[l], N = 4 * H;

        // input-weight plane + GEMM for xg
        split_w<<<(4 * H * KP + 255) / 256, 256>>>(Wih[l], wbh, H, K, KP);
        const __half* Asrc = (l == 0) ? ah : (ah + (size_t)BATCH * 1152);
        dim3 gg((N + 127) / 128, MROWS / 128);
        gemm_half<<<gg, 128, GEMM_SMEM>>>(Asrc, wbh, bb[l], xg, N, KP, H);

        // reset h-plane buffer (zeroes slot 0 and pad cols) + barrier flags
        cudaMemsetAsync(ah, 0, (size_t)(T_SEQ + 1) * BATCH * HP * 2);
        cudaMemsetAsync(flags, 0, 512 * sizeof(unsigned));

        // recurrent-weight plane
        split_w<<<(4 * H * HP + 255) / 256, 256>>>(Whh[l], wbh, H, H, HP);

        // persistent recurrent kernel: all 200 steps in one launch
        const int nblk = (N + 31) / 32;   // 144 or 50
        const int psm = (32 * (HP + 8) + 2 * (int)LSTG) * 2 + 128 * 36 * 4;
        lstm_persist<<<nblk, 256, psm>>>(xg, ah, wbh,
                                         out + outoff[l], flags, H, HP);
    }
}